// round 14
// baseline (speedup 1.0000x reference)
#include <cuda_runtime.h>
#include <cuda_bf16.h>
#include <math.h>
#include <stdint.h>

// Problem sizes
#define QN 512
#define LN 4096

// ---------------- scratch (device globals; no allocation allowed) ----------------
__device__ float g_p [LN * 256];     // relu(protein @ Wc.T + bc)
__device__ float g_k [LN * 64];      // relu(p @ W1.T + b1)
__device__ float g_pa[LN * 64];      // k @ Wpa.T + bpa
__device__ float g_S [(LN + QN) * 64]; // [0,LN*64): sum_q |ra+pa| ; [LN*64,..): sum_l |ra+pa|
__device__ float g_r [QN * 64];      // relu(reactions @ W2.T + b2)
__device__ float g_ra[QN * 64];      // r @ Wra.T + bra
__device__ float g_Spa[64];          // sum_l pa[l,j]
__device__ float g_Sra[64];          // sum_q ra[q,j]
__device__ float g_prot[64];         // max_l (k * (1+p_gate))
#define SR_OFF (LN * 64)

// =================== mma.sync bf16 helpers (hi/lo split) ===================
__device__ __forceinline__ void mma16816(float* c, const uint32_t* a, const uint32_t* b) {
    asm volatile(
        "mma.sync.aligned.m16n8k16.row.col.f32.bf16.bf16.f32 "
        "{%0,%1,%2,%3}, {%4,%5,%6,%7}, {%8,%9}, {%0,%1,%2,%3};\n"
        : "+f"(c[0]), "+f"(c[1]), "+f"(c[2]), "+f"(c[3])
        : "r"(a[0]), "r"(a[1]), "r"(a[2]), "r"(a[3]), "r"(b[0]), "r"(b[1]));
}

__device__ __forceinline__ uint32_t cvt2_bf16(float x, float y) {
    uint32_t r;
    asm("cvt.rn.bf16x2.f32 %0, %1, %2;" : "=r"(r) : "f"(y), "f"(x));
    return r;
}
__device__ __forceinline__ void split2(float x, float y, uint32_t& hi, uint32_t& lo) {
    hi = cvt2_bf16(x, y);
    float h0 = __uint_as_float(hi << 16);
    float h1 = __uint_as_float(hi & 0xffff0000u);
    lo = cvt2_bf16(x - h0, y - h1);
}
__device__ __forceinline__ void split_pack8(const float* f, uint4& hi, uint4& lo) {
    split2(f[0], f[1], hi.x, lo.x);
    split2(f[2], f[3], hi.y, lo.y);
    split2(f[4], f[5], hi.z, lo.z);
    split2(f[6], f[7], hi.w, lo.w);
}

#define SR 40

// ---------------- p-GEMM: BM=64 x BN=64, grid (4,64) => 2 CTA/SM ----------------
// stage: A hi 64x40 | A lo | B hi 64x40 | B lo = 10240 bf16 = 20480 B
#define STAGE64 (256 * SR)
#define GEMMP_SMEM_BYTES (2 * STAGE64 * 2)   // 40960 B

__global__ void __launch_bounds__(256)
gemm_p64(const float* __restrict__ A, const float* __restrict__ B,
         const float* __restrict__ bias, int K, int ldc, float* __restrict__ C) {
    extern __shared__ __nv_bfloat16 sm[];
    const int t    = threadIdx.x;
    const int lane = t & 31;
    const int wid  = t >> 5;
    const int wm   = wid >> 2;        // 0..1 (32 rows each)
    const int wn   = wid & 3;         // 0..3 (16 cols each)
    const int m0   = blockIdx.y * 64;
    const int n0   = blockIdx.x * 64;
    const int r    = lane >> 2;
    const int cq   = (lane & 3) * 2;

    float acc[2][2][4] = {};
    const int ar0 = t >> 2;           // 0..63
    const int au  = (t & 3) * 8;
    const int nch = K >> 5;

    float xA[8], xB[8], yA[8], yB[8];

    #define LDGP(k0, fa, fb) do {                                               \
        const float* _s0 = A + (size_t)(m0 + ar0) * K + (k0) + au;              \
        *(float4*)&fa[0] = *(const float4*)_s0;                                 \
        *(float4*)&fa[4] = *(const float4*)(_s0 + 4);                           \
        const float* _s1 = B + (size_t)(n0 + ar0) * K + (k0) + au;              \
        *(float4*)&fb[0] = *(const float4*)_s1;                                 \
        *(float4*)&fb[4] = *(const float4*)(_s1 + 4);                           \
    } while (0)

    #define STSP(st, fa, fb) do {                                               \
        __nv_bfloat16* base = sm + (st) * STAGE64;                              \
        uint4 hi, lo;                                                           \
        split_pack8(fa, hi, lo);                                                \
        *(uint4*)(base + ar0 * SR + au)            = hi;                        \
        *(uint4*)(base + 64 * SR + ar0 * SR + au)  = lo;                        \
        split_pack8(fb, hi, lo);                                                \
        *(uint4*)(base + 128 * SR + ar0 * SR + au) = hi;                        \
        *(uint4*)(base + 192 * SR + ar0 * SR + au) = lo;                        \
    } while (0)

    #define COMPP(st) do {                                                      \
        const __nv_bfloat16* Ah = sm + (st) * STAGE64;                          \
        const __nv_bfloat16* Al = Ah + 64 * SR;                                 \
        const __nv_bfloat16* Bh = Ah + 128 * SR;                                \
        const __nv_bfloat16* Bl = Ah + 192 * SR;                                \
        _Pragma("unroll")                                                       \
        for (int ks = 0; ks < 2; ks++) {                                        \
            const int ka = ks * 16 + cq;                                        \
            uint32_t ah[2][4], al2[2][4], bh[2][2], bl[2][2];                   \
            _Pragma("unroll")                                                   \
            for (int ti = 0; ti < 2; ti++) {                                    \
                int row = wm * 32 + ti * 16 + r;                                \
                ah[ti][0] = *(const uint32_t*)(Ah + row * SR + ka);             \
                ah[ti][1] = *(const uint32_t*)(Ah + (row + 8) * SR + ka);       \
                ah[ti][2] = *(const uint32_t*)(Ah + row * SR + ka + 8);         \
                ah[ti][3] = *(const uint32_t*)(Ah + (row + 8) * SR + ka + 8);   \
                al2[ti][0] = *(const uint32_t*)(Al + row * SR + ka);            \
                al2[ti][1] = *(const uint32_t*)(Al + (row + 8) * SR + ka);      \
                al2[ti][2] = *(const uint32_t*)(Al + row * SR + ka + 8);        \
                al2[ti][3] = *(const uint32_t*)(Al + (row + 8) * SR + ka + 8);  \
            }                                                                   \
            _Pragma("unroll")                                                   \
            for (int tj = 0; tj < 2; tj++) {                                    \
                int col = wn * 16 + tj * 8 + r;                                 \
                bh[tj][0] = *(const uint32_t*)(Bh + col * SR + ka);             \
                bh[tj][1] = *(const uint32_t*)(Bh + col * SR + ka + 8);         \
                bl[tj][0] = *(const uint32_t*)(Bl + col * SR + ka);             \
                bl[tj][1] = *(const uint32_t*)(Bl + col * SR + ka + 8);         \
            }                                                                   \
            _Pragma("unroll")                                                   \
            for (int ti = 0; ti < 2; ti++)                                      \
                _Pragma("unroll")                                               \
                for (int tj = 0; tj < 2; tj++) {                                \
                    mma16816(acc[ti][tj], ah[ti], bh[tj]);                      \
                    mma16816(acc[ti][tj], ah[ti], bl[tj]);                      \
                    mma16816(acc[ti][tj], al2[ti], bh[tj]);                     \
                }                                                               \
        }                                                                       \
    } while (0)

    LDGP(0, xA, xB);
    #pragma unroll 1
    for (int c = 0; c < nch; c += 2) {
        LDGP((c + 1) << 5, yA, yB);
        STSP(0, xA, xB);
        __syncthreads();
        COMPP(0);
        if (c + 2 < nch) LDGP((c + 2) << 5, xA, xB);
        STSP(1, yA, yB);
        __syncthreads();
        COMPP(1);
    }
    #undef LDGP
    #undef STSP
    #undef COMPP

    #pragma unroll
    for (int ti = 0; ti < 2; ti++) {
        int row = m0 + wm * 32 + ti * 16 + r;
        #pragma unroll
        for (int tj = 0; tj < 2; tj++) {
            int col = n0 + wn * 16 + tj * 8 + cq;
            float b0 = __ldg(bias + col), b1 = __ldg(bias + col + 1);
            *(float2*)&C[(size_t)row * ldc + col] =
                make_float2(fmaxf(acc[ti][tj][0] + b0, 0.f), fmaxf(acc[ti][tj][1] + b1, 0.f));
            *(float2*)&C[(size_t)(row + 8) * ldc + col] =
                make_float2(fmaxf(acc[ti][tj][2] + b0, 0.f), fmaxf(acc[ti][tj][3] + b1, 0.f));
        }
    }
}

// ---------------- k+pa fused GEMM: BM=32, grid 128 (halved serial chain) ----------
// stage: A hi 32x40 | A lo | B hi 64x40 | B lo = 7680 bf16 = 15360 B
#define STAGE32 (192 * SR)
#define GEMM32_SMEM_BYTES (2 * STAGE32 * 2)  // 30720 B
#define SR2 72
#define U_KH 0
#define U_KL (32 * SR2)
#define U_WH (64 * SR2)
#define U_WL (128 * SR2)   // ends at 192*72 = 13824 elems <= 2*STAGE32

__global__ void __launch_bounds__(256)
gemm32_kpa(const float* __restrict__ A, const float* __restrict__ B,
           const float* __restrict__ bias, float* __restrict__ C,
           const float* __restrict__ W2p, const float* __restrict__ b2p,
           float* __restrict__ C2) {
    extern __shared__ __nv_bfloat16 sm[];
    const int t    = threadIdx.x;
    const int lane = t & 31;
    const int wid  = t >> 5;
    const int wm   = wid >> 2;        // 0..1 (16 rows each)
    const int wn   = wid & 3;         // 0..3 (16 cols each)
    const int m0   = blockIdx.y * 32;
    const int r    = lane >> 2;
    const int cq   = (lane & 3) * 2;
    const int K    = 256;

    float acc[2][4] = {};
    const int ar0 = t >> 2;           // 0..63 (B rows); A uses t<128 -> rows 0..31
    const int au  = (t & 3) * 8;

    float xA[8], xB[8], yA[8], yB[8];

    #define LDG32(k0, fa, fb) do {                                              \
        if (t < 128) {                                                          \
            const float* _s0 = A + (size_t)(m0 + ar0) * K + (k0) + au;          \
            *(float4*)&fa[0] = *(const float4*)_s0;                             \
            *(float4*)&fa[4] = *(const float4*)(_s0 + 4);                       \
        }                                                                       \
        const float* _s1 = B + (size_t)ar0 * K + (k0) + au;                     \
        *(float4*)&fb[0] = *(const float4*)_s1;                                 \
        *(float4*)&fb[4] = *(const float4*)(_s1 + 4);                           \
    } while (0)

    #define STS32(st, fa, fb) do {                                              \
        __nv_bfloat16* base = sm + (st) * STAGE32;                              \
        uint4 hi, lo;                                                           \
        if (t < 128) {                                                          \
            split_pack8(fa, hi, lo);                                            \
            *(uint4*)(base + ar0 * SR + au)           = hi;                     \
            *(uint4*)(base + 32 * SR + ar0 * SR + au) = lo;                     \
        }                                                                       \
        split_pack8(fb, hi, lo);                                                \
        *(uint4*)(base + 64 * SR + ar0 * SR + au)  = hi;                        \
        *(uint4*)(base + 128 * SR + ar0 * SR + au) = lo;                        \
    } while (0)

    #define COMP32(st) do {                                                     \
        const __nv_bfloat16* Ah = sm + (st) * STAGE32;                          \
        const __nv_bfloat16* Al = Ah + 32 * SR;                                 \
        const __nv_bfloat16* Bh = Ah + 64 * SR;                                 \
        const __nv_bfloat16* Bl = Ah + 128 * SR;                                \
        _Pragma("unroll")                                                       \
        for (int ks = 0; ks < 2; ks++) {                                        \
            const int ka = ks * 16 + cq;                                        \
            uint32_t ah[4], al2[4], bh[2][2], bl[2][2];                         \
            {                                                                   \
                int row = wm * 16 + r;                                          \
                ah[0] = *(const uint32_t*)(Ah + row * SR + ka);                 \
                ah[1] = *(const uint32_t*)(Ah + (row + 8) * SR + ka);           \
                ah[2] = *(const uint32_t*)(Ah + row * SR + ka + 8);             \
                ah[3] = *(const uint32_t*)(Ah + (row + 8) * SR + ka + 8);       \
                al2[0] = *(const uint32_t*)(Al + row * SR + ka);                \
                al2[1] = *(const uint32_t*)(Al + (row + 8) * SR + ka);          \
                al2[2] = *(const uint32_t*)(Al + row * SR + ka + 8);            \
                al2[3] = *(const uint32_t*)(Al + (row + 8) * SR + ka + 8);      \
            }                                                                   \
            _Pragma("unroll")                                                   \
            for (int tj = 0; tj < 2; tj++) {                                    \
                int col = wn * 16 + tj * 8 + r;                                 \
                bh[tj][0] = *(const uint32_t*)(Bh + col * SR + ka);             \
                bh[tj][1] = *(const uint32_t*)(Bh + col * SR + ka + 8);         \
                bl[tj][0] = *(const uint32_t*)(Bl + col * SR + ka);             \
                bl[tj][1] = *(const uint32_t*)(Bl + col * SR + ka + 8);         \
            }                                                                   \
            _Pragma("unroll")                                                   \
            for (int tj = 0; tj < 2; tj++) {                                    \
                mma16816(acc[tj], ah, bh[tj]);                                  \
                mma16816(acc[tj], ah, bl[tj]);                                  \
                mma16816(acc[tj], al2, bh[tj]);                                 \
            }                                                                   \
        }                                                                       \
    } while (0)

    LDG32(0, xA, xB);
    #pragma unroll 1
    for (int c = 0; c < 8; c += 2) {
        LDG32((c + 1) << 5, yA, yB);
        STS32(0, xA, xB);
        __syncthreads();
        COMP32(0);
        if (c + 2 < 8) LDG32((c + 2) << 5, xA, xB);
        STS32(1, yA, yB);
        __syncthreads();
        COMP32(1);
    }
    #undef LDG32
    #undef STS32
    #undef COMP32

    __syncthreads();  // done reading stages; tail reuses smem

    // epilogue: k = relu(acc+bias) -> gmem + smem split (rows 0..31 local)
    {
        int lr = wm * 16 + r;
        #pragma unroll
        for (int tj = 0; tj < 2; tj++) {
            int col = wn * 16 + tj * 8 + cq;
            float b0 = __ldg(bias + col), b1 = __ldg(bias + col + 1);
            float v00 = fmaxf(acc[tj][0] + b0, 0.f);
            float v01 = fmaxf(acc[tj][1] + b1, 0.f);
            float v10 = fmaxf(acc[tj][2] + b0, 0.f);
            float v11 = fmaxf(acc[tj][3] + b1, 0.f);
            *(float2*)&C[(size_t)(m0 + lr) * 64 + col]     = make_float2(v00, v01);
            *(float2*)&C[(size_t)(m0 + lr + 8) * 64 + col] = make_float2(v10, v11);
            uint32_t hi, lo;
            split2(v00, v01, hi, lo);
            *(uint32_t*)(sm + U_KH + lr * SR2 + col) = hi;
            *(uint32_t*)(sm + U_KL + lr * SR2 + col) = lo;
            split2(v10, v11, hi, lo);
            *(uint32_t*)(sm + U_KH + (lr + 8) * SR2 + col) = hi;
            *(uint32_t*)(sm + U_KL + (lr + 8) * SR2 + col) = lo;
        }
    }
    // Wpa split (64x64)
    #pragma unroll
    for (int i = t; i < 4096; i += 256) {
        int rw = i >> 6, cw = i & 63;
        float w = __ldg(W2p + i);
        __nv_bfloat16 h = __float2bfloat16_rn(w);
        sm[U_WH + rw * SR2 + cw] = h;
        sm[U_WL + rw * SR2 + cw] = __float2bfloat16_rn(w - __bfloat162float(h));
    }
    __syncthreads();

    // tail: pa = k @ Wpa.T + bpa   (M=32, N=64, K2=64)
    float acc2[2][4] = {};
    #pragma unroll
    for (int ks = 0; ks < 4; ks++) {
        const int ka = ks * 16 + cq;
        uint32_t ah[4], al2[4], bh[2][2], bl[2][2];
        {
            int row = wm * 16 + r;
            ah[0] = *(const uint32_t*)(sm + U_KH + row * SR2 + ka);
            ah[1] = *(const uint32_t*)(sm + U_KH + (row + 8) * SR2 + ka);
            ah[2] = *(const uint32_t*)(sm + U_KH + row * SR2 + ka + 8);
            ah[3] = *(const uint32_t*)(sm + U_KH + (row + 8) * SR2 + ka + 8);
            al2[0] = *(const uint32_t*)(sm + U_KL + row * SR2 + ka);
            al2[1] = *(const uint32_t*)(sm + U_KL + (row + 8) * SR2 + ka);
            al2[2] = *(const uint32_t*)(sm + U_KL + row * SR2 + ka + 8);
            al2[3] = *(const uint32_t*)(sm + U_KL + (row + 8) * SR2 + ka + 8);
        }
        #pragma unroll
        for (int tj = 0; tj < 2; tj++) {
            int col = wn * 16 + tj * 8 + r;
            bh[tj][0] = *(const uint32_t*)(sm + U_WH + col * SR2 + ka);
            bh[tj][1] = *(const uint32_t*)(sm + U_WH + col * SR2 + ka + 8);
            bl[tj][0] = *(const uint32_t*)(sm + U_WL + col * SR2 + ka);
            bl[tj][1] = *(const uint32_t*)(sm + U_WL + col * SR2 + ka + 8);
        }
        #pragma unroll
        for (int tj = 0; tj < 2; tj++) {
            mma16816(acc2[tj], ah, bh[tj]);
            mma16816(acc2[tj], ah, bl[tj]);
            mma16816(acc2[tj], al2, bh[tj]);
        }
    }
    {
        int row = m0 + wm * 16 + r;
        #pragma unroll
        for (int tj = 0; tj < 2; tj++) {
            int col = wn * 16 + tj * 8 + cq;
            float b0 = __ldg(b2p + col), b1 = __ldg(b2p + col + 1);
            *(float2*)&C2[(size_t)row * 64 + col] =
                make_float2(acc2[tj][0] + b0, acc2[tj][1] + b1);
            *(float2*)&C2[(size_t)(row + 8) * 64 + col] =
                make_float2(acc2[tj][2] + b0, acc2[tj][3] + b1);
        }
    }
}

// ---------------- r + ra fused (SIMT fp32, exact): grid (1,64) ----------------
__global__ void __launch_bounds__(256)
r_ra_kernel(const float* __restrict__ A, const float* __restrict__ B,
            const float* __restrict__ bias, const float* __restrict__ Wra,
            const float* __restrict__ bra,
            float* __restrict__ R, float* __restrict__ RA) {
    __shared__ float As[16][12];
    __shared__ float Bs[16][68];
    __shared__ float rs[8][66];
    __shared__ float Ws[64][65];
    const int t  = threadIdx.x;
    const int tx = t % 32;
    const int ty = t / 32;
    const int m0 = blockIdx.y * 8;
    const int K = 256, N = 64;
    float a0 = 0.f, a1 = 0.f;

    if (blockIdx.y == 0 && t < 64) {    // zero small accumulators (ordered via evR)
        g_Spa[t] = 0.f; g_Sra[t] = 0.f; g_prot[t] = 0.f;
    }

    for (int k0 = 0; k0 < K; k0 += 16) {
        for (int i = t; i < 32; i += 256) {
            int rr = i / 4, cc = (i % 4) * 4;
            float4 v = *(const float4*)&A[(m0 + rr) * K + k0 + cc];
            As[cc + 0][rr] = v.x; As[cc + 1][rr] = v.y;
            As[cc + 2][rr] = v.z; As[cc + 3][rr] = v.w;
        }
        for (int i = t; i < 256; i += 256) {
            int rr = i / 4, cc = (i % 4) * 4;
            float4 v = *(const float4*)&B[(rr) * K + k0 + cc];
            Bs[cc + 0][rr] = v.x; Bs[cc + 1][rr] = v.y;
            Bs[cc + 2][rr] = v.z; Bs[cc + 3][rr] = v.w;
        }
        __syncthreads();
        #pragma unroll
        for (int kk = 0; kk < 16; kk++) {
            float a = As[kk][ty];
            a0 = fmaf(a, Bs[kk][tx * 2 + 0], a0);
            a1 = fmaf(a, Bs[kk][tx * 2 + 1], a1);
        }
        __syncthreads();
    }
    {
        int c0 = tx * 2;
        float v0 = fmaxf(a0 + bias[c0], 0.f);
        float v1 = fmaxf(a1 + bias[c0 + 1], 0.f);
        rs[ty][c0] = v0; rs[ty][c0 + 1] = v1;
        *(float2*)&R[(size_t)(m0 + ty) * N + c0] = make_float2(v0, v1);
    }
    for (int i = t; i < 4096; i += 256) Ws[i >> 6][i & 63] = Wra[i];
    __syncthreads();
    {
        int j = t & 63, g = t >> 6;
        float s0 = 0.f, s1 = 0.f;
        #pragma unroll
        for (int c = 0; c < 64; c++) {
            float w = Ws[j][c];
            s0 = fmaf(rs[g][c], w, s0);
            s1 = fmaf(rs[g + 4][c], w, s1);
        }
        float bj = bra[j];
        RA[(size_t)(m0 + g) * 64 + j]     = s0 + bj;
        RA[(size_t)(m0 + g + 4) * 64 + j] = s1 + bj;
    }
}

// ---------------- abs-sum double reduction, packed f32x2 ----------------
__global__ void __launch_bounds__(256, 2)
relusum_kernel(const float* __restrict__ ra, const float* __restrict__ pa) {
    extern __shared__ float smf[];
    float* ra_s = smf;             // 64*64
    float* sr_s = smf + 64 * 64;   // 4*64*64
    int t = threadIdx.x;
    int j = t & 63, g = t >> 6;
    int l0 = blockIdx.x * 128;
    int q0 = blockIdx.y * 64;
    int lb = l0 + g * 32;

    unsigned long long pa2[16], sp2[16];
    #pragma unroll
    for (int i = 0; i < 16; i++) {
        float x0 = pa[(lb + 2 * i) * 64 + j];
        float x1 = pa[(lb + 2 * i + 1) * 64 + j];
        asm("mov.b64 %0, {%1, %2};" : "=l"(pa2[i]) : "f"(x0), "f"(x1));
        sp2[i] = 0ULL;
    }
    for (int i = t; i < 1024; i += 256)
        ((float4*)ra_s)[i] = ((const float4*)(ra + q0 * 64))[i];
    __syncthreads();

    if (blockIdx.y == 0) {            // pa column partial sums
        float s = 0.f;
        #pragma unroll
        for (int i = 0; i < 16; i++) {
            float lo, hi;
            asm("mov.b64 {%0, %1}, %2;" : "=f"(lo), "=f"(hi) : "l"(pa2[i]));
            s += lo + hi;
        }
        atomicAdd(&g_Spa[j], s);
    }
    if (blockIdx.x == 0) {            // ra column partial sums
        float s = 0.f;
        #pragma unroll
        for (int qq = 0; qq < 16; qq++) s += ra_s[(g * 16 + qq) * 64 + j];
        atomicAdd(&g_Sra[j], s);
    }

    #define ADD2(d, a, b) asm("add.rn.f32x2 %0, %1, %2;" : "=l"(d) : "l"(a), "l"(b))
    #define AND2(d, a)    asm("and.b64 %0, %1, 0x7FFFFFFF7FFFFFFF;" : "=l"(d) : "l"(a))
    #pragma unroll 2
    for (int q = 0; q < 64; q++) {
        float raq = ra_s[q * 64 + j];
        unsigned long long raq2;
        asm("mov.b64 %0, {%1, %1};" : "=l"(raq2) : "f"(raq));
        unsigned long long sa = 0ULL, sb = 0ULL, sc = 0ULL, sd = 0ULL;
        #pragma unroll
        for (int i = 0; i < 16; i += 4) {
            unsigned long long v0, v1, v2, v3, a0, a1, a2, a3;
            ADD2(v0, pa2[i + 0], raq2);
            ADD2(v1, pa2[i + 1], raq2);
            ADD2(v2, pa2[i + 2], raq2);
            ADD2(v3, pa2[i + 3], raq2);
            AND2(a0, v0); AND2(a1, v1); AND2(a2, v2); AND2(a3, v3);
            ADD2(sp2[i + 0], sp2[i + 0], a0);
            ADD2(sp2[i + 1], sp2[i + 1], a1);
            ADD2(sp2[i + 2], sp2[i + 2], a2);
            ADD2(sp2[i + 3], sp2[i + 3], a3);
            ADD2(sa, sa, a0); ADD2(sb, sb, a1);
            ADD2(sc, sc, a2); ADD2(sd, sd, a3);
        }
        unsigned long long sab, scd, s2;
        ADD2(sab, sa, sb); ADD2(scd, sc, sd); ADD2(s2, sab, scd);
        float slo, shi;
        asm("mov.b64 {%0, %1}, %2;" : "=f"(slo), "=f"(shi) : "l"(s2));
        sr_s[(g * 64 + q) * 64 + j] = slo + shi;
    }
    #undef ADD2
    #undef AND2
    __syncthreads();

    #pragma unroll
    for (int i = 0; i < 16; i++) {
        float lo, hi;
        asm("mov.b64 {%0, %1}, %2;" : "=f"(lo), "=f"(hi) : "l"(sp2[i]));
        atomicAdd(&g_S[(lb + 2 * i) * 64 + j], lo);
        atomicAdd(&g_S[(lb + 2 * i + 1) * 64 + j], hi);
    }
    for (int idx = t; idx < 4096; idx += 256) {
        int q = idx >> 6, jj = idx & 63;
        float s = (sr_s[q * 64 + jj] + sr_s[(64 + q) * 64 + jj]) +
                  (sr_s[(128 + q) * 64 + jj] + sr_s[(192 + q) * 64 + jj]);
        atomicAdd(&g_S[SR_OFF + (q0 + q) * 64 + jj], s);
    }
}

// ---------------- p_gate / prot: S_p = 0.5*(Q*pa + Sra + abs) ----------------
__global__ void __launch_bounds__(256)
pgate_prot_kernel(const float* __restrict__ Wa, const float* __restrict__ ba) {
    __shared__ float Ws[64][65];
    __shared__ float sps[64][64];
    __shared__ float red[4][64];
    int t = threadIdx.x;
    int j = t & 63, g = t >> 6;
    int l0 = blockIdx.x * 64;
    for (int i = t; i < 4096; i += 256) Ws[i >> 6][i & 63] = Wa[i];
    for (int i = t; i < 1024; i += 256) {
        float4 ab = ((const float4*)(g_S + l0 * 64))[i];
        float4 p4 = ((const float4*)(g_pa + l0 * 64))[i];
        int c0 = (i * 4) & 63;
        float4 sr4 = *(const float4*)(g_Sra + c0);
        float4 o;
        o.x = 0.5f * (512.f * p4.x + sr4.x + ab.x);
        o.y = 0.5f * (512.f * p4.y + sr4.y + ab.y);
        o.z = 0.5f * (512.f * p4.z + sr4.z + ab.z);
        o.w = 0.5f * (512.f * p4.w + sr4.w + ab.w);
        ((float4*)sps)[i] = o;
    }
    __syncthreads();
    float acc[16] = {};
    for (int c = 0; c < 64; c++) {
        float w = Ws[j][c];
        #pragma unroll
        for (int rr = 0; rr < 16; rr++)
            acc[rr] = fmaf(sps[rr * 4 + g][c], w, acc[rr]);
    }
    float bj = ba[j];
    float mx = 0.f;
    #pragma unroll
    for (int rr = 0; rr < 16; rr++) {
        int l = l0 + rr * 4 + g;
        float gate = 1.f / (1.f + expf(-(acc[rr] * (1.f / 512.f) + bj)));
        float cand = g_k[l * 64 + j] * (1.f + gate);  // k>=0 -> cand>=0
        mx = fmaxf(mx, cand);
    }
    red[g][j] = mx;
    __syncthreads();
    if (t < 64) {
        float m = fmaxf(fmaxf(red[0][t], red[1][t]), fmaxf(red[2][t], red[3][t]));
        atomicMax(reinterpret_cast<unsigned*>(&g_prot[t]), __float_as_uint(m));
    }
}

// ---------------- r_gate, ctx, MLP: S_r = 0.5*(L*ra + Spa + abs) ----------------
__global__ void __launch_bounds__(256)
final_kernel(const float* __restrict__ Wa,  const float* __restrict__ ba,
             const float* __restrict__ Wf1, const float* __restrict__ bf1,
             const float* __restrict__ Wf2, const float* __restrict__ bf2,
             const float* __restrict__ Wf3, const float* __restrict__ bf3,
             float* __restrict__ out) {
    __shared__ float Ws[64][65];
    __shared__ float srs[8][64];
    __shared__ float rs[8][64];
    __shared__ float ctx[8][128];
    __shared__ float h1s[8][256];
    __shared__ float h2s[8][128];
    __shared__ float prot_s[64];
    int t = threadIdx.x;
    int q0 = blockIdx.x * 8;
    for (int i = t; i < 4096; i += 256) Ws[i >> 6][i & 63] = Wa[i];
    if (t < 128) {
        float4 ab  = ((const float4*)(g_S + SR_OFF + q0 * 64))[t];
        float4 ra4 = ((const float4*)(g_ra + q0 * 64))[t];
        int c0 = (t * 4) & 63;
        float4 sp4 = *(const float4*)(g_Spa + c0);
        float4 o;
        o.x = 0.5f * (4096.f * ra4.x + sp4.x + ab.x);
        o.y = 0.5f * (4096.f * ra4.y + sp4.y + ab.y);
        o.z = 0.5f * (4096.f * ra4.z + sp4.z + ab.z);
        o.w = 0.5f * (4096.f * ra4.w + sp4.w + ab.w);
        ((float4*)srs)[t] = o;
        ((float4*)rs)[t]  = ((const float4*)(g_r + q0 * 64))[t];
    }
    if (t < 64) prot_s[t] = g_prot[t];
    __syncthreads();
    {
        int j = t & 63, g = t >> 6;
        float a0 = 0.f, a1 = 0.f;
        for (int c = 0; c < 64; c++) {
            float w = Ws[j][c];
            a0 = fmaf(srs[g][c], w, a0);
            a1 = fmaf(srs[g + 4][c], w, a1);
        }
        float bj = ba[j];
        float g0 = 1.f / (1.f + expf(-(a0 * (1.f / 4096.f) + bj)));
        float g1 = 1.f / (1.f + expf(-(a1 * (1.f / 4096.f) + bj)));
        ctx[g][j]          = rs[g][j]     * (1.f + g0);
        ctx[g + 4][j]      = rs[g + 4][j] * (1.f + g1);
        ctx[g][64 + j]     = prot_s[j];
        ctx[g + 4][64 + j] = prot_s[j];
    }
    __syncthreads();
    {
        float acc[8] = {};
        const float* wrow = Wf1 + t * 128;
        for (int c = 0; c < 128; c++) {
            float w = wrow[c];
            #pragma unroll
            for (int qq = 0; qq < 8; qq++)
                acc[qq] = fmaf(ctx[qq][c], w, acc[qq]);
        }
        float bj = bf1[t];
        #pragma unroll
        for (int qq = 0; qq < 8; qq++) {
            float v = acc[qq] + bj;
            h1s[qq][t] = v >= 0.f ? v : 0.01f * v;
        }
    }
    __syncthreads();
    {
        int jj = t & 127, h = t >> 7;
        float acc[4] = {};
        const float* wrow = Wf2 + jj * 256;
        for (int c = 0; c < 256; c++) {
            float w = wrow[c];
            #pragma unroll
            for (int qq = 0; qq < 4; qq++)
                acc[qq] = fmaf(h1s[h * 4 + qq][c], w, acc[qq]);
        }
        float bj = bf2[jj];
        #pragma unroll
        for (int qq = 0; qq < 4; qq++) {
            float v = acc[qq] + bj;
            h2s[h * 4 + qq][jj] = v >= 0.f ? v : 0.01f * v;
        }
    }
    __syncthreads();
    {
        int w = t >> 5, lane = t & 31;
        float s = 0.f;
        #pragma unroll
        for (int k4 = 0; k4 < 4; k4++)
            s = fmaf(h2s[w][lane + k4 * 32], Wf3[lane + k4 * 32], s);
        #pragma unroll
        for (int off = 16; off > 0; off >>= 1)
            s += __shfl_down_sync(0xffffffff, s, off);
        if (lane == 0) out[q0 + w] = s + bf3[0];
    }
}

// ---------------- launch ----------------
extern "C" void kernel_launch(void* const* d_in, const int* in_sizes, int n_in,
                              void* d_out, int out_size) {
    const float* reactions = (const float*)d_in[0];
    const float* protein   = (const float*)d_in[1];
    const float* Wc  = (const float*)d_in[2];
    const float* bc  = (const float*)d_in[3];
    const float* W1  = (const float*)d_in[4];
    const float* b1  = (const float*)d_in[5];
    const float* W2  = (const float*)d_in[6];
    const float* b2  = (const float*)d_in[7];
    const float* Wa  = (const float*)d_in[8];
    const float* ba  = (const float*)d_in[9];
    const float* Wpa = (const float*)d_in[10];
    const float* bpa = (const float*)d_in[11];
    const float* Wra = (const float*)d_in[12];
    const float* bra = (const float*)d_in[13];
    const float* Wf1 = (const float*)d_in[14];
    const float* bf1 = (const float*)d_in[15];
    const float* Wf2 = (const float*)d_in[16];
    const float* bf2 = (const float*)d_in[17];
    const float* Wf3 = (const float*)d_in[18];
    const float* bf3 = (const float*)d_in[19];
    float* out = (float*)d_out;

    float *pP, *pK, *pPa, *pR, *pRa, *pS;
    cudaGetSymbolAddress((void**)&pP,  g_p);
    cudaGetSymbolAddress((void**)&pK,  g_k);
    cudaGetSymbolAddress((void**)&pPa, g_pa);
    cudaGetSymbolAddress((void**)&pR,  g_r);
    cudaGetSymbolAddress((void**)&pRa, g_ra);
    cudaGetSymbolAddress((void**)&pS,  g_S);

    static cudaStream_t s1 = nullptr, s2 = nullptr;
    static cudaEvent_t evF = nullptr, evR = nullptr, evZ = nullptr;
    if (!s1) {
        cudaStreamCreateWithFlags(&s1, cudaStreamNonBlocking);
        cudaStreamCreateWithFlags(&s2, cudaStreamNonBlocking);
        cudaEventCreateWithFlags(&evF, cudaEventDisableTiming);
        cudaEventCreateWithFlags(&evR, cudaEventDisableTiming);
        cudaEventCreateWithFlags(&evZ, cudaEventDisableTiming);
        cudaFuncSetAttribute(gemm_p64,
                             cudaFuncAttributeMaxDynamicSharedMemorySize, GEMMP_SMEM_BYTES);
        cudaFuncSetAttribute(gemm32_kpa,
                             cudaFuncAttributeMaxDynamicSharedMemorySize, GEMM32_SMEM_BYTES);
        cudaFuncSetAttribute(relusum_kernel,
                             cudaFuncAttributeMaxDynamicSharedMemorySize,
                             (64 * 64 + 4 * 64 * 64) * 4);
    }

    // ---- fork ----
    cudaEventRecord(evF, 0);
    cudaStreamWaitEvent(s1, evF, 0);
    cudaStreamWaitEvent(s2, evF, 0);

    // s2: zero the merged abs-sum accumulator (one node)
    cudaMemsetAsync(pS, 0, (size_t)(LN + QN) * 64 * sizeof(float), s2);
    cudaEventRecord(evZ, s2);

    // s1: reaction branch r -> ra (also zeroes g_Spa/g_Sra/g_prot)
    r_ra_kernel<<<dim3(1, 64), 256, 0, s1>>>(reactions, W2, b2, Wra, bra, pR, pRa);
    cudaEventRecord(evR, s1);

    // main: protein chain  p -> (k + pa fused)
    gemm_p64<<<dim3(4, 64), 256, GEMMP_SMEM_BYTES>>>(protein, Wc, bc, 1024, 256, pP);
    gemm32_kpa<<<dim3(1, 128), 256, GEMM32_SMEM_BYTES>>>(pP, W1, b1, pK, Wpa, bpa, pPa);

    // ---- join ----
    cudaStreamWaitEvent(0, evR, 0);
    cudaStreamWaitEvent(0, evZ, 0);

    // abs-sum double reduction, packed f32x2 (relu = (x+|x|)/2 downstream)
    const int rsmem = (64 * 64 + 4 * 64 * 64) * 4;
    relusum_kernel<<<dim3(32, 8), 256, rsmem>>>(pRa, pPa);

    pgate_prot_kernel<<<64, 256>>>(Wa, ba);
    final_kernel<<<64, 256>>>(Wa, ba, Wf1, bf1, Wf2, bf2, Wf3, bf3, out);
}

// round 15
// speedup vs baseline: 1.0797x; 1.0797x over previous
#include <cuda_runtime.h>
#include <cuda_bf16.h>
#include <math.h>
#include <stdint.h>

// Problem sizes
#define QN 512
#define LN 4096

// ---------------- scratch (device globals; no allocation allowed) ----------------
__device__ float g_p [LN * 256];   // relu(protein @ Wc.T + bc)
__device__ float g_k [LN * 64];    // relu(p @ W1.T + b1)
__device__ float g_pa[LN * 64];    // k @ Wpa.T + bpa
__device__ float g_Sp[LN * 64];    // sum_q |ra+pa|  (abs-sums; relu recovered later)
__device__ float g_r [QN * 64];    // relu(reactions @ W2.T + b2)
__device__ float g_ra[QN * 64];    // r @ Wra.T + bra
__device__ float g_Sr[QN * 64];    // sum_l |ra+pa|
__device__ float g_Spa[64];        // sum_l pa[l,j]
__device__ float g_Sra[64];        // sum_q ra[q,j]
__device__ float g_prot[64];       // max_l (k * (1+p_gate))
__device__ unsigned g_ctr;         // pgate->final intra-kernel sync counter

// =================== mma.sync bf16 helpers (hi/lo split) ===================
__device__ __forceinline__ void mma16816(float* c, const uint32_t* a, const uint32_t* b) {
    asm volatile(
        "mma.sync.aligned.m16n8k16.row.col.f32.bf16.bf16.f32 "
        "{%0,%1,%2,%3}, {%4,%5,%6,%7}, {%8,%9}, {%0,%1,%2,%3};\n"
        : "+f"(c[0]), "+f"(c[1]), "+f"(c[2]), "+f"(c[3])
        : "r"(a[0]), "r"(a[1]), "r"(a[2]), "r"(a[3]), "r"(b[0]), "r"(b[1]));
}

// packed: d = {low = x(bf16), high = y(bf16)}, round-nearest
__device__ __forceinline__ uint32_t cvt2_bf16(float x, float y) {
    uint32_t r;
    asm("cvt.rn.bf16x2.f32 %0, %1, %2;" : "=r"(r) : "f"(y), "f"(x));
    return r;
}
__device__ __forceinline__ void split2(float x, float y, uint32_t& hi, uint32_t& lo) {
    hi = cvt2_bf16(x, y);
    float h0 = __uint_as_float(hi << 16);
    float h1 = __uint_as_float(hi & 0xffff0000u);
    lo = cvt2_bf16(x - h0, y - h1);
}
__device__ __forceinline__ void split_pack8(const float* f, uint4& hi, uint4& lo) {
    split2(f[0], f[1], hi.x, lo.x);
    split2(f[2], f[3], hi.y, lo.y);
    split2(f[4], f[5], hi.z, lo.z);
    split2(f[6], f[7], hi.w, lo.w);
}

// ---------------- p-GEMM: 128x64 CTA tile, C = relu(A@B.T + bias) ----------------
#define SR 40
#define ST_AL (128 * SR)
#define ST_BH (2 * 128 * SR)
#define ST_BL (2 * 128 * SR + 64 * SR)
#define STAGE (2 * 128 * SR + 2 * 64 * SR)   // 15360 bf16 = 30720 B
#define GEMM_SMEM_BYTES (2 * STAGE * 2)      // 61440 B

__global__ void __launch_bounds__(256)
gemm_p(const float* __restrict__ A, const float* __restrict__ B,
       const float* __restrict__ bias, int K, int ldc, float* __restrict__ C) {
    extern __shared__ __nv_bfloat16 sm[];
    const int t    = threadIdx.x;
    const int lane = t & 31;
    const int wid  = t >> 5;
    const int wm   = wid >> 1;
    const int wn   = wid & 1;
    const int m0   = blockIdx.y * 128;
    const int n0   = blockIdx.x * 64;
    const int r    = lane >> 2;
    const int cq   = (lane & 3) * 2;

    float acc[2][4][4] = {};
    const int ar0 = t >> 2;
    const int au  = (t & 3) * 8;
    const int nch = K >> 5;

    float xA0[8], xA1[8], xB0[8];
    float yA0[8], yA1[8], yB0[8];

    #define LDG_CHUNK(k0, fa0, fa1, fb) do {                                    \
        const float* _s0 = A + (size_t)(m0 + ar0) * K + (k0) + au;              \
        *(float4*)&fa0[0] = *(const float4*)_s0;                                \
        *(float4*)&fa0[4] = *(const float4*)(_s0 + 4);                          \
        const float* _s1 = A + (size_t)(m0 + ar0 + 64) * K + (k0) + au;         \
        *(float4*)&fa1[0] = *(const float4*)_s1;                                \
        *(float4*)&fa1[4] = *(const float4*)(_s1 + 4);                          \
        const float* _s2 = B + (size_t)(n0 + ar0) * K + (k0) + au;              \
        *(float4*)&fb[0]  = *(const float4*)_s2;                                \
        *(float4*)&fb[4]  = *(const float4*)(_s2 + 4);                          \
    } while (0)

    #define STS_CHUNK(st, fa0, fa1, fb) do {                                    \
        __nv_bfloat16* base = sm + (st) * STAGE;                                \
        uint4 hi, lo;                                                           \
        split_pack8(fa0, hi, lo);                                               \
        *(uint4*)(base + ar0 * SR + au)                = hi;                    \
        *(uint4*)(base + ST_AL + ar0 * SR + au)        = lo;                    \
        split_pack8(fa1, hi, lo);                                               \
        *(uint4*)(base + (ar0 + 64) * SR + au)         = hi;                    \
        *(uint4*)(base + ST_AL + (ar0 + 64) * SR + au) = lo;                    \
        split_pack8(fb, hi, lo);                                                \
        *(uint4*)(base + ST_BH + ar0 * SR + au)        = hi;                    \
        *(uint4*)(base + ST_BL + ar0 * SR + au)        = lo;                    \
    } while (0)

    #define COMPUTE_CHUNK(st) do {                                              \
        const __nv_bfloat16* Ah = sm + (st) * STAGE;                            \
        const __nv_bfloat16* Al = Ah + ST_AL;                                   \
        const __nv_bfloat16* Bh = Ah + ST_BH;                                   \
        const __nv_bfloat16* Bl = Ah + ST_BL;                                   \
        _Pragma("unroll")                                                       \
        for (int ks = 0; ks < 2; ks++) {                                        \
            const int ka = ks * 16 + cq;                                        \
            uint32_t ah[2][4], al[2][4], bh[4][2], bl[4][2];                    \
            _Pragma("unroll")                                                   \
            for (int ti = 0; ti < 2; ti++) {                                    \
                int row = wm * 32 + ti * 16 + r;                                \
                ah[ti][0] = *(const uint32_t*)(Ah + row * SR + ka);             \
                ah[ti][1] = *(const uint32_t*)(Ah + (row + 8) * SR + ka);       \
                ah[ti][2] = *(const uint32_t*)(Ah + row * SR + ka + 8);         \
                ah[ti][3] = *(const uint32_t*)(Ah + (row + 8) * SR + ka + 8);   \
                al[ti][0] = *(const uint32_t*)(Al + row * SR + ka);             \
                al[ti][1] = *(const uint32_t*)(Al + (row + 8) * SR + ka);       \
                al[ti][2] = *(const uint32_t*)(Al + row * SR + ka + 8);         \
                al[ti][3] = *(const uint32_t*)(Al + (row + 8) * SR + ka + 8);   \
            }                                                                   \
            _Pragma("unroll")                                                   \
            for (int tj = 0; tj < 4; tj++) {                                    \
                int col = wn * 32 + tj * 8 + r;                                 \
                bh[tj][0] = *(const uint32_t*)(Bh + col * SR + ka);             \
                bh[tj][1] = *(const uint32_t*)(Bh + col * SR + ka + 8);         \
                bl[tj][0] = *(const uint32_t*)(Bl + col * SR + ka);             \
                bl[tj][1] = *(const uint32_t*)(Bl + col * SR + ka + 8);         \
            }                                                                   \
            _Pragma("unroll")                                                   \
            for (int ti = 0; ti < 2; ti++)                                      \
                _Pragma("unroll")                                               \
                for (int tj = 0; tj < 4; tj++) {                                \
                    mma16816(acc[ti][tj], ah[ti], bh[tj]);                      \
                    mma16816(acc[ti][tj], ah[ti], bl[tj]);                      \
                    mma16816(acc[ti][tj], al[ti], bh[tj]);                      \
                }                                                               \
        }                                                                       \
    } while (0)

    LDG_CHUNK(0, xA0, xA1, xB0);
    #pragma unroll 1
    for (int c = 0; c < nch; c += 2) {
        LDG_CHUNK((c + 1) << 5, yA0, yA1, yB0);
        STS_CHUNK(0, xA0, xA1, xB0);
        __syncthreads();
        COMPUTE_CHUNK(0);
        if (c + 2 < nch) LDG_CHUNK((c + 2) << 5, xA0, xA1, xB0);
        STS_CHUNK(1, yA0, yA1, yB0);
        __syncthreads();
        COMPUTE_CHUNK(1);
    }
    #undef LDG_CHUNK
    #undef STS_CHUNK
    #undef COMPUTE_CHUNK

    #pragma unroll
    for (int ti = 0; ti < 2; ti++) {
        int row = m0 + wm * 32 + ti * 16 + r;
        #pragma unroll
        for (int tj = 0; tj < 4; tj++) {
            int col = n0 + wn * 32 + tj * 8 + cq;
            float b0 = __ldg(bias + col), b1 = __ldg(bias + col + 1);
            *(float2*)&C[(size_t)row * ldc + col] =
                make_float2(fmaxf(acc[ti][tj][0] + b0, 0.f), fmaxf(acc[ti][tj][1] + b1, 0.f));
            *(float2*)&C[(size_t)(row + 8) * ldc + col] =
                make_float2(fmaxf(acc[ti][tj][2] + b0, 0.f), fmaxf(acc[ti][tj][3] + b1, 0.f));
        }
    }
}

// ---------------- k+pa fused GEMM: BM=64, grid 64 ----------------
#define STAGE64 (256 * SR)                   // 10240 bf16 = 20480 B per stage
#define GEMM64_SMEM_BYTES (2 * STAGE64 * 2)  // 40960 B
#define SR2 72
#define U_KH 0
#define U_KL (64 * SR2)
#define U_WH (128 * SR2)
#define U_WL (192 * SR2)

__global__ void __launch_bounds__(256)
gemm64_kpa(const float* __restrict__ A, const float* __restrict__ B,
           const float* __restrict__ bias, float* __restrict__ C,
           const float* __restrict__ W2p, const float* __restrict__ b2p,
           float* __restrict__ C2) {
    extern __shared__ __nv_bfloat16 sm[];
    const int t    = threadIdx.x;
    const int lane = t & 31;
    const int wid  = t >> 5;
    const int wm   = wid >> 2;        // 0..1
    const int wn   = wid & 3;         // 0..3
    const int m0   = blockIdx.y * 64;
    const int r    = lane >> 2;
    const int cq   = (lane & 3) * 2;
    const int K    = 256;

    float acc[2][2][4] = {};
    const int ar0 = t >> 2;           // 0..63
    const int au  = (t & 3) * 8;

    float xA[8], xB[8], yA[8], yB[8];

    #define LDG64(k0, fa, fb) do {                                              \
        const float* _s0 = A + (size_t)(m0 + ar0) * K + (k0) + au;              \
        *(float4*)&fa[0] = *(const float4*)_s0;                                 \
        *(float4*)&fa[4] = *(const float4*)(_s0 + 4);                           \
        const float* _s1 = B + (size_t)ar0 * K + (k0) + au;                     \
        *(float4*)&fb[0] = *(const float4*)_s1;                                 \
        *(float4*)&fb[4] = *(const float4*)(_s1 + 4);                           \
    } while (0)

    #define STS64(st, fa, fb) do {                                              \
        __nv_bfloat16* base = sm + (st) * STAGE64;                              \
        uint4 hi, lo;                                                           \
        split_pack8(fa, hi, lo);                                                \
        *(uint4*)(base + ar0 * SR + au)            = hi;                        \
        *(uint4*)(base + 64 * SR + ar0 * SR + au)  = lo;                        \
        split_pack8(fb, hi, lo);                                                \
        *(uint4*)(base + 128 * SR + ar0 * SR + au) = hi;                        \
        *(uint4*)(base + 192 * SR + ar0 * SR + au) = lo;                        \
    } while (0)

    #define COMP64(st) do {                                                     \
        const __nv_bfloat16* Ah = sm + (st) * STAGE64;                          \
        const __nv_bfloat16* Al = Ah + 64 * SR;                                 \
        const __nv_bfloat16* Bh = Ah + 128 * SR;                                \
        const __nv_bfloat16* Bl = Ah + 192 * SR;                                \
        _Pragma("unroll")                                                       \
        for (int ks = 0; ks < 2; ks++) {                                        \
            const int ka = ks * 16 + cq;                                        \
            uint32_t ah[2][4], al2[2][4], bh[2][2], bl[2][2];                   \
            _Pragma("unroll")                                                   \
            for (int ti = 0; ti < 2; ti++) {                                    \
                int row = wm * 32 + ti * 16 + r;                                \
                ah[ti][0] = *(const uint32_t*)(Ah + row * SR + ka);             \
                ah[ti][1] = *(const uint32_t*)(Ah + (row + 8) * SR + ka);       \
                ah[ti][2] = *(const uint32_t*)(Ah + row * SR + ka + 8);         \
                ah[ti][3] = *(const uint32_t*)(Ah + (row + 8) * SR + ka + 8);   \
                al2[ti][0] = *(const uint32_t*)(Al + row * SR + ka);            \
                al2[ti][1] = *(const uint32_t*)(Al + (row + 8) * SR + ka);      \
                al2[ti][2] = *(const uint32_t*)(Al + row * SR + ka + 8);        \
                al2[ti][3] = *(const uint32_t*)(Al + (row + 8) * SR + ka + 8);  \
            }                                                                   \
            _Pragma("unroll")                                                   \
            for (int tj = 0; tj < 2; tj++) {                                    \
                int col = wn * 16 + tj * 8 + r;                                 \
                bh[tj][0] = *(const uint32_t*)(Bh + col * SR + ka);             \
                bh[tj][1] = *(const uint32_t*)(Bh + col * SR + ka + 8);         \
                bl[tj][0] = *(const uint32_t*)(Bl + col * SR + ka);             \
                bl[tj][1] = *(const uint32_t*)(Bl + col * SR + ka + 8);         \
            }                                                                   \
            _Pragma("unroll")                                                   \
            for (int ti = 0; ti < 2; ti++)                                      \
                _Pragma("unroll")                                               \
                for (int tj = 0; tj < 2; tj++) {                                \
                    mma16816(acc[ti][tj], ah[ti], bh[tj]);                      \
                    mma16816(acc[ti][tj], ah[ti], bl[tj]);                      \
                    mma16816(acc[ti][tj], al2[ti], bh[tj]);                     \
                }                                                               \
        }                                                                       \
    } while (0)

    LDG64(0, xA, xB);
    #pragma unroll 1
    for (int c = 0; c < 8; c += 2) {
        LDG64((c + 1) << 5, yA, yB);
        STS64(0, xA, xB);
        __syncthreads();
        COMP64(0);
        if (c + 2 < 8) LDG64((c + 2) << 5, xA, xB);
        STS64(1, yA, yB);
        __syncthreads();
        COMP64(1);
    }
    #undef LDG64
    #undef STS64
    #undef COMP64

    __syncthreads();  // done reading stages; tail reuses smem

    // epilogue: k = relu(acc+bias) -> gmem + smem split
    #pragma unroll
    for (int ti = 0; ti < 2; ti++) {
        int lr = wm * 32 + ti * 16 + r;
        #pragma unroll
        for (int tj = 0; tj < 2; tj++) {
            int col = wn * 16 + tj * 8 + cq;
            float b0 = __ldg(bias + col), b1 = __ldg(bias + col + 1);
            float v00 = fmaxf(acc[ti][tj][0] + b0, 0.f);
            float v01 = fmaxf(acc[ti][tj][1] + b1, 0.f);
            float v10 = fmaxf(acc[ti][tj][2] + b0, 0.f);
            float v11 = fmaxf(acc[ti][tj][3] + b1, 0.f);
            *(float2*)&C[(size_t)(m0 + lr) * 64 + col]     = make_float2(v00, v01);
            *(float2*)&C[(size_t)(m0 + lr + 8) * 64 + col] = make_float2(v10, v11);
            uint32_t hi, lo;
            split2(v00, v01, hi, lo);
            *(uint32_t*)(sm + U_KH + lr * SR2 + col) = hi;
            *(uint32_t*)(sm + U_KL + lr * SR2 + col) = lo;
            split2(v10, v11, hi, lo);
            *(uint32_t*)(sm + U_KH + (lr + 8) * SR2 + col) = hi;
            *(uint32_t*)(sm + U_KL + (lr + 8) * SR2 + col) = lo;
        }
    }
    // Wpa split
    #pragma unroll
    for (int i = t; i < 4096; i += 256) {
        int rw = i >> 6, cw = i & 63;
        float w = __ldg(W2p + i);
        __nv_bfloat16 h = __float2bfloat16_rn(w);
        sm[U_WH + rw * SR2 + cw] = h;
        sm[U_WL + rw * SR2 + cw] = __float2bfloat16_rn(w - __bfloat162float(h));
    }
    __syncthreads();

    float acc2[2][2][4] = {};
    #pragma unroll
    for (int ks = 0; ks < 4; ks++) {
        const int ka = ks * 16 + cq;
        uint32_t ah[2][4], al2[2][4], bh[2][2], bl[2][2];
        #pragma unroll
        for (int ti = 0; ti < 2; ti++) {
            int row = wm * 32 + ti * 16 + r;
            ah[ti][0] = *(const uint32_t*)(sm + U_KH + row * SR2 + ka);
            ah[ti][1] = *(const uint32_t*)(sm + U_KH + (row + 8) * SR2 + ka);
            ah[ti][2] = *(const uint32_t*)(sm + U_KH + row * SR2 + ka + 8);
            ah[ti][3] = *(const uint32_t*)(sm + U_KH + (row + 8) * SR2 + ka + 8);
            al2[ti][0] = *(const uint32_t*)(sm + U_KL + row * SR2 + ka);
            al2[ti][1] = *(const uint32_t*)(sm + U_KL + (row + 8) * SR2 + ka);
            al2[ti][2] = *(const uint32_t*)(sm + U_KL + row * SR2 + ka + 8);
            al2[ti][3] = *(const uint32_t*)(sm + U_KL + (row + 8) * SR2 + ka + 8);
        }
        #pragma unroll
        for (int tj = 0; tj < 2; tj++) {
            int col = wn * 16 + tj * 8 + r;
            bh[tj][0] = *(const uint32_t*)(sm + U_WH + col * SR2 + ka);
            bh[tj][1] = *(const uint32_t*)(sm + U_WH + col * SR2 + ka + 8);
            bl[tj][0] = *(const uint32_t*)(sm + U_WL + col * SR2 + ka);
            bl[tj][1] = *(const uint32_t*)(sm + U_WL + col * SR2 + ka + 8);
        }
        #pragma unroll
        for (int ti = 0; ti < 2; ti++)
            #pragma unroll
            for (int tj = 0; tj < 2; tj++) {
                mma16816(acc2[ti][tj], ah[ti], bh[tj]);
                mma16816(acc2[ti][tj], ah[ti], bl[tj]);
                mma16816(acc2[ti][tj], al2[ti], bh[tj]);
            }
    }
    #pragma unroll
    for (int ti = 0; ti < 2; ti++) {
        int row = m0 + wm * 32 + ti * 16 + r;
        #pragma unroll
        for (int tj = 0; tj < 2; tj++) {
            int col = wn * 16 + tj * 8 + cq;
            float b0 = __ldg(b2p + col), b1 = __ldg(b2p + col + 1);
            *(float2*)&C2[(size_t)row * 64 + col] =
                make_float2(acc2[ti][tj][0] + b0, acc2[ti][tj][1] + b1);
            *(float2*)&C2[(size_t)(row + 8) * 64 + col] =
                make_float2(acc2[ti][tj][2] + b0, acc2[ti][tj][3] + b1);
        }
    }
}

// ---------------- r + ra fused (SIMT fp32, exact): grid (1,64) ----------------
__global__ void __launch_bounds__(256)
r_ra_kernel(const float* __restrict__ A, const float* __restrict__ B,
            const float* __restrict__ bias, const float* __restrict__ Wra,
            const float* __restrict__ bra,
            float* __restrict__ R, float* __restrict__ RA) {
    __shared__ float As[16][12];
    __shared__ float Bs[16][68];
    __shared__ float rs[8][66];
    __shared__ float Ws[64][65];
    const int t  = threadIdx.x;
    const int tx = t % 32;
    const int ty = t / 32;
    const int m0 = blockIdx.y * 8;
    const int K = 256, N = 64;
    float a0 = 0.f, a1 = 0.f;

    if (blockIdx.y == 0 && t < 64) {    // zero small accumulators (ordered via evR)
        g_Spa[t] = 0.f; g_Sra[t] = 0.f; g_prot[t] = 0.f;
        if (t == 0) g_ctr = 0u;
    }

    for (int k0 = 0; k0 < K; k0 += 16) {
        for (int i = t; i < 32; i += 256) {
            int rr = i / 4, cc = (i % 4) * 4;
            float4 v = *(const float4*)&A[(m0 + rr) * K + k0 + cc];
            As[cc + 0][rr] = v.x; As[cc + 1][rr] = v.y;
            As[cc + 2][rr] = v.z; As[cc + 3][rr] = v.w;
        }
        for (int i = t; i < 256; i += 256) {
            int rr = i / 4, cc = (i % 4) * 4;
            float4 v = *(const float4*)&B[(rr) * K + k0 + cc];
            Bs[cc + 0][rr] = v.x; Bs[cc + 1][rr] = v.y;
            Bs[cc + 2][rr] = v.z; Bs[cc + 3][rr] = v.w;
        }
        __syncthreads();
        #pragma unroll
        for (int kk = 0; kk < 16; kk++) {
            float a = As[kk][ty];
            a0 = fmaf(a, Bs[kk][tx * 2 + 0], a0);
            a1 = fmaf(a, Bs[kk][tx * 2 + 1], a1);
        }
        __syncthreads();
    }
    {
        int c0 = tx * 2;
        float v0 = fmaxf(a0 + bias[c0], 0.f);
        float v1 = fmaxf(a1 + bias[c0 + 1], 0.f);
        rs[ty][c0] = v0; rs[ty][c0 + 1] = v1;
        *(float2*)&R[(size_t)(m0 + ty) * N + c0] = make_float2(v0, v1);
    }
    for (int i = t; i < 4096; i += 256) Ws[i >> 6][i & 63] = Wra[i];
    __syncthreads();
    {
        int j = t & 63, g = t >> 6;
        float s0 = 0.f, s1 = 0.f;
        #pragma unroll
        for (int c = 0; c < 64; c++) {
            float w = Ws[j][c];
            s0 = fmaf(rs[g][c], w, s0);
            s1 = fmaf(rs[g + 4][c], w, s1);
        }
        float bj = bra[j];
        RA[(size_t)(m0 + g) * 64 + j]     = s0 + bj;
        RA[(size_t)(m0 + g + 4) * 64 + j] = s1 + bj;
    }
}

// ---------------- abs-sum double reduction, packed f32x2 ----------------
__global__ void __launch_bounds__(256, 2)
relusum_kernel(const float* __restrict__ ra, const float* __restrict__ pa) {
    extern __shared__ float smf[];
    float* ra_s = smf;             // 64*64
    float* sr_s = smf + 64 * 64;   // 4*64*64
    int t = threadIdx.x;
    int j = t & 63, g = t >> 6;
    int l0 = blockIdx.x * 128;
    int q0 = blockIdx.y * 64;
    int lb = l0 + g * 32;

    unsigned long long pa2[16], sp2[16];
    #pragma unroll
    for (int i = 0; i < 16; i++) {
        float x0 = pa[(lb + 2 * i) * 64 + j];
        float x1 = pa[(lb + 2 * i + 1) * 64 + j];
        asm("mov.b64 %0, {%1, %2};" : "=l"(pa2[i]) : "f"(x0), "f"(x1));
        sp2[i] = 0ULL;
    }
    for (int i = t; i < 1024; i += 256)
        ((float4*)ra_s)[i] = ((const float4*)(ra + q0 * 64))[i];
    __syncthreads();

    if (blockIdx.y == 0) {            // pa column partial sums
        float s = 0.f;
        #pragma unroll
        for (int i = 0; i < 16; i++) {
            float lo, hi;
            asm("mov.b64 {%0, %1}, %2;" : "=f"(lo), "=f"(hi) : "l"(pa2[i]));
            s += lo + hi;
        }
        atomicAdd(&g_Spa[j], s);
    }
    if (blockIdx.x == 0) {            // ra column partial sums
        float s = 0.f;
        #pragma unroll
        for (int qq = 0; qq < 16; qq++) s += ra_s[(g * 16 + qq) * 64 + j];
        atomicAdd(&g_Sra[j], s);
    }

    #define ADD2(d, a, b) asm("add.rn.f32x2 %0, %1, %2;" : "=l"(d) : "l"(a), "l"(b))
    #define AND2(d, a)    asm("and.b64 %0, %1, 0x7FFFFFFF7FFFFFFF;" : "=l"(d) : "l"(a))
    #pragma unroll 2
    for (int q = 0; q < 64; q++) {
        float raq = ra_s[q * 64 + j];
        unsigned long long raq2;
        asm("mov.b64 %0, {%1, %1};" : "=l"(raq2) : "f"(raq));
        unsigned long long sa = 0ULL, sb = 0ULL, sc = 0ULL, sd = 0ULL;
        #pragma unroll
        for (int i = 0; i < 16; i += 4) {
            unsigned long long v0, v1, v2, v3, a0, a1, a2, a3;
            ADD2(v0, pa2[i + 0], raq2);
            ADD2(v1, pa2[i + 1], raq2);
            ADD2(v2, pa2[i + 2], raq2);
            ADD2(v3, pa2[i + 3], raq2);
            AND2(a0, v0); AND2(a1, v1); AND2(a2, v2); AND2(a3, v3);
            ADD2(sp2[i + 0], sp2[i + 0], a0);
            ADD2(sp2[i + 1], sp2[i + 1], a1);
            ADD2(sp2[i + 2], sp2[i + 2], a2);
            ADD2(sp2[i + 3], sp2[i + 3], a3);
            ADD2(sa, sa, a0); ADD2(sb, sb, a1);
            ADD2(sc, sc, a2); ADD2(sd, sd, a3);
        }
        unsigned long long sab, scd, s2;
        ADD2(sab, sa, sb); ADD2(scd, sc, sd); ADD2(s2, sab, scd);
        float slo, shi;
        asm("mov.b64 {%0, %1}, %2;" : "=f"(slo), "=f"(shi) : "l"(s2));
        sr_s[(g * 64 + q) * 64 + j] = slo + shi;
    }
    #undef ADD2
    #undef AND2
    __syncthreads();

    #pragma unroll
    for (int i = 0; i < 16; i++) {
        float lo, hi;
        asm("mov.b64 {%0, %1}, %2;" : "=f"(lo), "=f"(hi) : "l"(sp2[i]));
        atomicAdd(&g_Sp[(lb + 2 * i) * 64 + j], lo);
        atomicAdd(&g_Sp[(lb + 2 * i + 1) * 64 + j], hi);
    }
    for (int idx = t; idx < 4096; idx += 256) {
        int q = idx >> 6, jj = idx & 63;
        float s = (sr_s[q * 64 + jj] + sr_s[(64 + q) * 64 + jj]) +
                  (sr_s[(128 + q) * 64 + jj] + sr_s[(192 + q) * 64 + jj]);
        atomicAdd(&g_Sr[(q0 + q) * 64 + jj], s);
    }
}

// ---------------- merged pgate + final, grid 128, device-side counter sync -----
// blocks 0..63: pgate  S_p = 0.5*(Q*pa + Sra + abs) -> prot (atomicMax) -> ctr++
// blocks 64..127: final (prot-independent work first, then spin on ctr==64)
#define GF_SMEM_FLOATS 9344   // max(pgate 8512, final 9344)
__global__ void __launch_bounds__(256)
gate_final_kernel(const float* __restrict__ Wa,  const float* __restrict__ ba,
                  const float* __restrict__ Wf1, const float* __restrict__ bf1,
                  const float* __restrict__ Wf2, const float* __restrict__ bf2,
                  const float* __restrict__ Wf3, const float* __restrict__ bf3,
                  float* __restrict__ out) {
    extern __shared__ float dsm[];
    float (*Ws)[65] = (float(*)[65])dsm;       // 64*65 = 4160 floats
    const int t = threadIdx.x;
    const int b = blockIdx.x;
    for (int i = t; i < 4096; i += 256) Ws[i >> 6][i & 63] = Wa[i];

    if (b < 64) {
        // ================= pgate part =================
        float (*sps)[64] = (float(*)[64])(dsm + 4160);        // 4096
        float (*red)[64] = (float(*)[64])(dsm + 4160 + 4096); // 256
        int j = t & 63, g = t >> 6;
        int l0 = b * 64;
        for (int i = t; i < 1024; i += 256) {
            float4 ab = ((const float4*)(g_Sp + l0 * 64))[i];
            float4 p4 = ((const float4*)(g_pa + l0 * 64))[i];
            int c0 = (i * 4) & 63;
            float4 sr4 = *(const float4*)(g_Sra + c0);
            float4 o;
            o.x = 0.5f * (512.f * p4.x + sr4.x + ab.x);
            o.y = 0.5f * (512.f * p4.y + sr4.y + ab.y);
            o.z = 0.5f * (512.f * p4.z + sr4.z + ab.z);
            o.w = 0.5f * (512.f * p4.w + sr4.w + ab.w);
            ((float4*)sps)[i] = o;
        }
        __syncthreads();
        float acc[16] = {};
        for (int c = 0; c < 64; c++) {
            float w = Ws[j][c];
            #pragma unroll
            for (int rr = 0; rr < 16; rr++)
                acc[rr] = fmaf(sps[rr * 4 + g][c], w, acc[rr]);
        }
        float bj = ba[j];
        float mx = 0.f;
        #pragma unroll
        for (int rr = 0; rr < 16; rr++) {
            int l = l0 + rr * 4 + g;
            float gate = 1.f / (1.f + expf(-(acc[rr] * (1.f / 512.f) + bj)));
            float cand = g_k[l * 64 + j] * (1.f + gate);  // k>=0 -> cand>=0
            mx = fmaxf(mx, cand);
        }
        red[g][j] = mx;
        __syncthreads();
        if (t < 64) {
            float m = fmaxf(fmaxf(red[0][t], red[1][t]), fmaxf(red[2][t], red[3][t]));
            atomicMax(reinterpret_cast<unsigned*>(&g_prot[t]), __float_as_uint(m));
            __threadfence();
        }
        __syncthreads();
        if (t == 0) atomicAdd(&g_ctr, 1u);
    } else {
        // ================= final part =================
        float (*srs)[64]  = (float(*)[64]) (dsm + 4160);          // 512
        float (*rs)[64]   = (float(*)[64]) (dsm + 4160 + 512);    // 512
        float (*ctx)[128] = (float(*)[128])(dsm + 4160 + 1024);   // 1024
        float (*h1s)[256] = (float(*)[256])(dsm + 4160 + 2048);   // 2048
        float (*h2s)[128] = (float(*)[128])(dsm + 4160 + 4096);   // 1024
        float* prot_s     = dsm + 4160 + 5120;                    // 64
        int q0 = (b - 64) * 8;
        if (t < 128) {
            float4 ab  = ((const float4*)(g_Sr + q0 * 64))[t];
            float4 ra4 = ((const float4*)(g_ra + q0 * 64))[t];
            int c0 = (t * 4) & 63;
            float4 sp4 = *(const float4*)(g_Spa + c0);
            float4 o;
            o.x = 0.5f * (4096.f * ra4.x + sp4.x + ab.x);
            o.y = 0.5f * (4096.f * ra4.y + sp4.y + ab.y);
            o.z = 0.5f * (4096.f * ra4.z + sp4.z + ab.z);
            o.w = 0.5f * (4096.f * ra4.w + sp4.w + ab.w);
            ((float4*)srs)[t] = o;
            ((float4*)rs)[t]  = ((const float4*)(g_r + q0 * 64))[t];
        }
        __syncthreads();
        // stage A (prot-independent): r_gate and the reaction half of ctx
        {
            int j = t & 63, g = t >> 6;
            float a0 = 0.f, a1 = 0.f;
            for (int c = 0; c < 64; c++) {
                float w = Ws[j][c];
                a0 = fmaf(srs[g][c], w, a0);
                a1 = fmaf(srs[g + 4][c], w, a1);
            }
            float bj = ba[j];
            float g0 = 1.f / (1.f + expf(-(a0 * (1.f / 4096.f) + bj)));
            float g1 = 1.f / (1.f + expf(-(a1 * (1.f / 4096.f) + bj)));
            ctx[g][j]     = rs[g][j]     * (1.f + g0);
            ctx[g + 4][j] = rs[g + 4][j] * (1.f + g1);
        }
        // wait for all pgate blocks, then read prot
        if (t == 0) {
            while (atomicAdd(&g_ctr, 0u) < 64u) { }
        }
        __syncthreads();
        if (t < 64) {
            float p = atomicAdd(&g_prot[t], 0.f);  // L2 atomic read (fresh)
            prot_s[t] = p;
        }
        __syncthreads();
        {
            int j = t & 63, g = t >> 6;
            ctx[g][64 + j]     = prot_s[j];
            ctx[g + 4][64 + j] = prot_s[j];
        }
        __syncthreads();
        {
            float acc[8] = {};
            const float* wrow = Wf1 + t * 128;
            for (int c = 0; c < 128; c++) {
                float w = wrow[c];
                #pragma unroll
                for (int qq = 0; qq < 8; qq++)
                    acc[qq] = fmaf(ctx[qq][c], w, acc[qq]);
            }
            float bj = bf1[t];
            #pragma unroll
            for (int qq = 0; qq < 8; qq++) {
                float v = acc[qq] + bj;
                h1s[qq][t] = v >= 0.f ? v : 0.01f * v;
            }
        }
        __syncthreads();
        {
            int jj = t & 127, h = t >> 7;
            float acc[4] = {};
            const float* wrow = Wf2 + jj * 256;
            for (int c = 0; c < 256; c++) {
                float w = wrow[c];
                #pragma unroll
                for (int qq = 0; qq < 4; qq++)
                    acc[qq] = fmaf(h1s[h * 4 + qq][c], w, acc[qq]);
            }
            float bj = bf2[jj];
            #pragma unroll
            for (int qq = 0; qq < 4; qq++) {
                float v = acc[qq] + bj;
                h2s[h * 4 + qq][jj] = v >= 0.f ? v : 0.01f * v;
            }
        }
        __syncthreads();
        {
            int w = t >> 5, lane = t & 31;
            float s = 0.f;
            #pragma unroll
            for (int k4 = 0; k4 < 4; k4++)
                s = fmaf(h2s[w][lane + k4 * 32], Wf3[lane + k4 * 32], s);
            #pragma unroll
            for (int off = 16; off > 0; off >>= 1)
                s += __shfl_down_sync(0xffffffff, s, off);
            if (lane == 0) out[q0 + w] = s + bf3[0];
        }
    }
}

// ---------------- launch ----------------
extern "C" void kernel_launch(void* const* d_in, const int* in_sizes, int n_in,
                              void* d_out, int out_size) {
    const float* reactions = (const float*)d_in[0];
    const float* protein   = (const float*)d_in[1];
    const float* Wc  = (const float*)d_in[2];
    const float* bc  = (const float*)d_in[3];
    const float* W1  = (const float*)d_in[4];
    const float* b1  = (const float*)d_in[5];
    const float* W2  = (const float*)d_in[6];
    const float* b2  = (const float*)d_in[7];
    const float* Wa  = (const float*)d_in[8];
    const float* ba  = (const float*)d_in[9];
    const float* Wpa = (const float*)d_in[10];
    const float* bpa = (const float*)d_in[11];
    const float* Wra = (const float*)d_in[12];
    const float* bra = (const float*)d_in[13];
    const float* Wf1 = (const float*)d_in[14];
    const float* bf1 = (const float*)d_in[15];
    const float* Wf2 = (const float*)d_in[16];
    const float* bf2 = (const float*)d_in[17];
    const float* Wf3 = (const float*)d_in[18];
    const float* bf3 = (const float*)d_in[19];
    float* out = (float*)d_out;

    float *pP, *pK, *pPa, *pR, *pRa, *pSp, *pSr;
    cudaGetSymbolAddress((void**)&pP,  g_p);
    cudaGetSymbolAddress((void**)&pK,  g_k);
    cudaGetSymbolAddress((void**)&pPa, g_pa);
    cudaGetSymbolAddress((void**)&pR,  g_r);
    cudaGetSymbolAddress((void**)&pRa, g_ra);
    cudaGetSymbolAddress((void**)&pSp, g_Sp);
    cudaGetSymbolAddress((void**)&pSr, g_Sr);

    static cudaStream_t s1 = nullptr, s2 = nullptr;
    static cudaEvent_t evF = nullptr, evR = nullptr, evZ = nullptr;
    if (!s1) {
        cudaStreamCreateWithFlags(&s1, cudaStreamNonBlocking);
        cudaStreamCreateWithFlags(&s2, cudaStreamNonBlocking);
        cudaEventCreateWithFlags(&evF, cudaEventDisableTiming);
        cudaEventCreateWithFlags(&evR, cudaEventDisableTiming);
        cudaEventCreateWithFlags(&evZ, cudaEventDisableTiming);
        cudaFuncSetAttribute(gemm_p,
                             cudaFuncAttributeMaxDynamicSharedMemorySize, GEMM_SMEM_BYTES);
        cudaFuncSetAttribute(gemm64_kpa,
                             cudaFuncAttributeMaxDynamicSharedMemorySize, GEMM64_SMEM_BYTES);
        cudaFuncSetAttribute(relusum_kernel,
                             cudaFuncAttributeMaxDynamicSharedMemorySize,
                             (64 * 64 + 4 * 64 * 64) * 4);
    }

    // ---- fork ----
    cudaEventRecord(evF, 0);
    cudaStreamWaitEvent(s1, evF, 0);
    cudaStreamWaitEvent(s2, evF, 0);

    // s2: zero the abs-sum accumulators
    cudaMemsetAsync(pSp, 0, (size_t)LN * 64 * sizeof(float), s2);
    cudaMemsetAsync(pSr, 0, (size_t)QN * 64 * sizeof(float), s2);
    cudaEventRecord(evZ, s2);

    // s1: reaction branch r -> ra (also zeroes g_Spa/g_Sra/g_prot/g_ctr)
    r_ra_kernel<<<dim3(1, 64), 256, 0, s1>>>(reactions, W2, b2, Wra, bra, pR, pRa);
    cudaEventRecord(evR, s1);

    // main: protein chain  p -> (k + pa fused)
    gemm_p<<<dim3(4, 32), 256, GEMM_SMEM_BYTES>>>(protein, Wc, bc, 1024, 256, pP);
    gemm64_kpa<<<dim3(1, 64), 256, GEMM64_SMEM_BYTES>>>(pP, W1, b1, pK, Wpa, bpa, pPa);

    // ---- join ----
    cudaStreamWaitEvent(0, evR, 0);
    cudaStreamWaitEvent(0, evZ, 0);

    // abs-sum double reduction, packed f32x2 (relu = (x+|x|)/2 downstream)
    const int rsmem = (64 * 64 + 4 * 64 * 64) * 4;
    relusum_kernel<<<dim3(32, 8), 256, rsmem>>>(pRa, pPa);

    // merged pgate + final (device-side counter sync; 128 blocks co-resident)
    gate_final_kernel<<<128, 256, GF_SMEM_FLOATS * sizeof(float)>>>(
        Wa, ba, Wf1, bf1, Wf2, bf2, Wf3, bf3, out);
}

// round 16
// speedup vs baseline: 1.2090x; 1.1198x over previous
#include <cuda_runtime.h>
#include <cuda_bf16.h>
#include <math.h>
#include <stdint.h>

// Problem sizes
#define QN 512
#define LN 4096

// ---------------- scratch (device globals; no allocation allowed) ----------------
__device__ float g_p [LN * 256];   // relu(protein @ Wc.T + bc)
__device__ float g_k [LN * 64];    // relu(p @ W1.T + b1)
__device__ float g_pa[LN * 64];    // k @ Wpa.T + bpa
__device__ float g_Sp[LN * 64];    // sum_q |ra+pa|  (abs-sums; relu recovered later)
__device__ float g_r [QN * 64];    // relu(reactions @ W2.T + b2)
__device__ float g_ra[QN * 64];    // r @ Wra.T + bra
__device__ float g_Sr[QN * 64];    // sum_l |ra+pa|
__device__ float g_Spa[64];        // sum_l pa[l,j]
__device__ float g_Sra[64];        // sum_q ra[q,j]
__device__ float g_prot[64];       // max_l (k * (1+p_gate))

// =================== mma.sync bf16 helpers (hi/lo split) ===================
__device__ __forceinline__ void mma16816(float* c, const uint32_t* a, const uint32_t* b) {
    asm volatile(
        "mma.sync.aligned.m16n8k16.row.col.f32.bf16.bf16.f32 "
        "{%0,%1,%2,%3}, {%4,%5,%6,%7}, {%8,%9}, {%0,%1,%2,%3};\n"
        : "+f"(c[0]), "+f"(c[1]), "+f"(c[2]), "+f"(c[3])
        : "r"(a[0]), "r"(a[1]), "r"(a[2]), "r"(a[3]), "r"(b[0]), "r"(b[1]));
}

// packed: d = {low = x(bf16), high = y(bf16)}, round-nearest
__device__ __forceinline__ uint32_t cvt2_bf16(float x, float y) {
    uint32_t r;
    asm("cvt.rn.bf16x2.f32 %0, %1, %2;" : "=r"(r) : "f"(y), "f"(x));
    return r;
}
__device__ __forceinline__ void split2(float x, float y, uint32_t& hi, uint32_t& lo) {
    hi = cvt2_bf16(x, y);
    float h0 = __uint_as_float(hi << 16);
    float h1 = __uint_as_float(hi & 0xffff0000u);
    lo = cvt2_bf16(x - h0, y - h1);
}
__device__ __forceinline__ void split_pack8(const float* f, uint4& hi, uint4& lo) {
    split2(f[0], f[1], hi.x, lo.x);
    split2(f[2], f[3], hi.y, lo.y);
    split2(f[4], f[5], hi.z, lo.z);
    split2(f[6], f[7], hi.w, lo.w);
}

// ---------------- p-GEMM: 128x64 CTA tile, C = relu(A@B.T + bias) ----------------
#define SR 40
#define ST_AL (128 * SR)
#define ST_BH (2 * 128 * SR)
#define ST_BL (2 * 128 * SR + 64 * SR)
#define STAGE (2 * 128 * SR + 2 * 64 * SR)   // 15360 bf16 = 30720 B
#define GEMM_SMEM_BYTES (2 * STAGE * 2)      // 61440 B

__global__ void __launch_bounds__(256)
gemm_p(const float* __restrict__ A, const float* __restrict__ B,
       const float* __restrict__ bias, int K, int ldc, float* __restrict__ C) {
    extern __shared__ __nv_bfloat16 sm[];
    const int t    = threadIdx.x;
    const int lane = t & 31;
    const int wid  = t >> 5;
    const int wm   = wid >> 1;
    const int wn   = wid & 1;
    const int m0   = blockIdx.y * 128;
    const int n0   = blockIdx.x * 64;
    const int r    = lane >> 2;
    const int cq   = (lane & 3) * 2;

    float acc[2][4][4] = {};
    const int ar0 = t >> 2;
    const int au  = (t & 3) * 8;
    const int nch = K >> 5;

    float xA0[8], xA1[8], xB0[8];
    float yA0[8], yA1[8], yB0[8];

    #define LDG_CHUNK(k0, fa0, fa1, fb) do {                                    \
        const float* _s0 = A + (size_t)(m0 + ar0) * K + (k0) + au;              \
        *(float4*)&fa0[0] = *(const float4*)_s0;                                \
        *(float4*)&fa0[4] = *(const float4*)(_s0 + 4);                          \
        const float* _s1 = A + (size_t)(m0 + ar0 + 64) * K + (k0) + au;         \
        *(float4*)&fa1[0] = *(const float4*)_s1;                                \
        *(float4*)&fa1[4] = *(const float4*)(_s1 + 4);                          \
        const float* _s2 = B + (size_t)(n0 + ar0) * K + (k0) + au;              \
        *(float4*)&fb[0]  = *(const float4*)_s2;                                \
        *(float4*)&fb[4]  = *(const float4*)(_s2 + 4);                          \
    } while (0)

    #define STS_CHUNK(st, fa0, fa1, fb) do {                                    \
        __nv_bfloat16* base = sm + (st) * STAGE;                                \
        uint4 hi, lo;                                                           \
        split_pack8(fa0, hi, lo);                                               \
        *(uint4*)(base + ar0 * SR + au)                = hi;                    \
        *(uint4*)(base + ST_AL + ar0 * SR + au)        = lo;                    \
        split_pack8(fa1, hi, lo);                                               \
        *(uint4*)(base + (ar0 + 64) * SR + au)         = hi;                    \
        *(uint4*)(base + ST_AL + (ar0 + 64) * SR + au) = lo;                    \
        split_pack8(fb, hi, lo);                                                \
        *(uint4*)(base + ST_BH + ar0 * SR + au)        = hi;                    \
        *(uint4*)(base + ST_BL + ar0 * SR + au)        = lo;                    \
    } while (0)

    #define COMPUTE_CHUNK(st) do {                                              \
        const __nv_bfloat16* Ah = sm + (st) * STAGE;                            \
        const __nv_bfloat16* Al = Ah + ST_AL;                                   \
        const __nv_bfloat16* Bh = Ah + ST_BH;                                   \
        const __nv_bfloat16* Bl = Ah + ST_BL;                                   \
        _Pragma("unroll")                                                       \
        for (int ks = 0; ks < 2; ks++) {                                        \
            const int ka = ks * 16 + cq;                                        \
            uint32_t ah[2][4], al[2][4], bh[4][2], bl[4][2];                    \
            _Pragma("unroll")                                                   \
            for (int ti = 0; ti < 2; ti++) {                                    \
                int row = wm * 32 + ti * 16 + r;                                \
                ah[ti][0] = *(const uint32_t*)(Ah + row * SR + ka);             \
                ah[ti][1] = *(const uint32_t*)(Ah + (row + 8) * SR + ka);       \
                ah[ti][2] = *(const uint32_t*)(Ah + row * SR + ka + 8);         \
                ah[ti][3] = *(const uint32_t*)(Ah + (row + 8) * SR + ka + 8);   \
                al[ti][0] = *(const uint32_t*)(Al + row * SR + ka);             \
                al[ti][1] = *(const uint32_t*)(Al + (row + 8) * SR + ka);       \
                al[ti][2] = *(const uint32_t*)(Al + row * SR + ka + 8);         \
                al[ti][3] = *(const uint32_t*)(Al + (row + 8) * SR + ka + 8);   \
            }                                                                   \
            _Pragma("unroll")                                                   \
            for (int tj = 0; tj < 4; tj++) {                                    \
                int col = wn * 32 + tj * 8 + r;                                 \
                bh[tj][0] = *(const uint32_t*)(Bh + col * SR + ka);             \
                bh[tj][1] = *(const uint32_t*)(Bh + col * SR + ka + 8);         \
                bl[tj][0] = *(const uint32_t*)(Bl + col * SR + ka);             \
                bl[tj][1] = *(const uint32_t*)(Bl + col * SR + ka + 8);         \
            }                                                                   \
            _Pragma("unroll")                                                   \
            for (int ti = 0; ti < 2; ti++)                                      \
                _Pragma("unroll")                                               \
                for (int tj = 0; tj < 4; tj++) {                                \
                    mma16816(acc[ti][tj], ah[ti], bh[tj]);                      \
                    mma16816(acc[ti][tj], ah[ti], bl[tj]);                      \
                    mma16816(acc[ti][tj], al[ti], bh[tj]);                      \
                }                                                               \
        }                                                                       \
    } while (0)

    LDG_CHUNK(0, xA0, xA1, xB0);
    #pragma unroll 1
    for (int c = 0; c < nch; c += 2) {
        LDG_CHUNK((c + 1) << 5, yA0, yA1, yB0);
        STS_CHUNK(0, xA0, xA1, xB0);
        __syncthreads();
        COMPUTE_CHUNK(0);
        if (c + 2 < nch) LDG_CHUNK((c + 2) << 5, xA0, xA1, xB0);
        STS_CHUNK(1, yA0, yA1, yB0);
        __syncthreads();
        COMPUTE_CHUNK(1);
    }
    #undef LDG_CHUNK
    #undef STS_CHUNK
    #undef COMPUTE_CHUNK

    #pragma unroll
    for (int ti = 0; ti < 2; ti++) {
        int row = m0 + wm * 32 + ti * 16 + r;
        #pragma unroll
        for (int tj = 0; tj < 4; tj++) {
            int col = n0 + wn * 32 + tj * 8 + cq;
            float b0 = __ldg(bias + col), b1 = __ldg(bias + col + 1);
            *(float2*)&C[(size_t)row * ldc + col] =
                make_float2(fmaxf(acc[ti][tj][0] + b0, 0.f), fmaxf(acc[ti][tj][1] + b1, 0.f));
            *(float2*)&C[(size_t)(row + 8) * ldc + col] =
                make_float2(fmaxf(acc[ti][tj][2] + b0, 0.f), fmaxf(acc[ti][tj][3] + b1, 0.f));
        }
    }
}

// ---------------- k+pa fused GEMM: BM=64, grid 64 ----------------
#define STAGE64 (256 * SR)                   // 10240 bf16 = 20480 B per stage
#define GEMM64_SMEM_BYTES (2 * STAGE64 * 2)  // 40960 B
#define SR2 72
#define U_KH 0
#define U_KL (64 * SR2)
#define U_WH (128 * SR2)
#define U_WL (192 * SR2)

__global__ void __launch_bounds__(256)
gemm64_kpa(const float* __restrict__ A, const float* __restrict__ B,
           const float* __restrict__ bias, float* __restrict__ C,
           const float* __restrict__ W2p, const float* __restrict__ b2p,
           float* __restrict__ C2) {
    extern __shared__ __nv_bfloat16 sm[];
    const int t    = threadIdx.x;
    const int lane = t & 31;
    const int wid  = t >> 5;
    const int wm   = wid >> 2;        // 0..1
    const int wn   = wid & 3;         // 0..3
    const int m0   = blockIdx.y * 64;
    const int r    = lane >> 2;
    const int cq   = (lane & 3) * 2;
    const int K    = 256;

    float acc[2][2][4] = {};
    const int ar0 = t >> 2;           // 0..63
    const int au  = (t & 3) * 8;

    float xA[8], xB[8], yA[8], yB[8];

    #define LDG64(k0, fa, fb) do {                                              \
        const float* _s0 = A + (size_t)(m0 + ar0) * K + (k0) + au;              \
        *(float4*)&fa[0] = *(const float4*)_s0;                                 \
        *(float4*)&fa[4] = *(const float4*)(_s0 + 4);                           \
        const float* _s1 = B + (size_t)ar0 * K + (k0) + au;                     \
        *(float4*)&fb[0] = *(const float4*)_s1;                                 \
        *(float4*)&fb[4] = *(const float4*)(_s1 + 4);                           \
    } while (0)

    #define STS64(st, fa, fb) do {                                              \
        __nv_bfloat16* base = sm + (st) * STAGE64;                              \
        uint4 hi, lo;                                                           \
        split_pack8(fa, hi, lo);                                                \
        *(uint4*)(base + ar0 * SR + au)            = hi;                        \
        *(uint4*)(base + 64 * SR + ar0 * SR + au)  = lo;                        \
        split_pack8(fb, hi, lo);                                                \
        *(uint4*)(base + 128 * SR + ar0 * SR + au) = hi;                        \
        *(uint4*)(base + 192 * SR + ar0 * SR + au) = lo;                        \
    } while (0)

    #define COMP64(st) do {                                                     \
        const __nv_bfloat16* Ah = sm + (st) * STAGE64;                          \
        const __nv_bfloat16* Al = Ah + 64 * SR;                                 \
        const __nv_bfloat16* Bh = Ah + 128 * SR;                                \
        const __nv_bfloat16* Bl = Ah + 192 * SR;                                \
        _Pragma("unroll")                                                       \
        for (int ks = 0; ks < 2; ks++) {                                        \
            const int ka = ks * 16 + cq;                                        \
            uint32_t ah[2][4], al2[2][4], bh[2][2], bl[2][2];                   \
            _Pragma("unroll")                                                   \
            for (int ti = 0; ti < 2; ti++) {                                    \
                int row = wm * 32 + ti * 16 + r;                                \
                ah[ti][0] = *(const uint32_t*)(Ah + row * SR + ka);             \
                ah[ti][1] = *(const uint32_t*)(Ah + (row + 8) * SR + ka);       \
                ah[ti][2] = *(const uint32_t*)(Ah + row * SR + ka + 8);         \
                ah[ti][3] = *(const uint32_t*)(Ah + (row + 8) * SR + ka + 8);   \
                al2[ti][0] = *(const uint32_t*)(Al + row * SR + ka);            \
                al2[ti][1] = *(const uint32_t*)(Al + (row + 8) * SR + ka);      \
                al2[ti][2] = *(const uint32_t*)(Al + row * SR + ka + 8);        \
                al2[ti][3] = *(const uint32_t*)(Al + (row + 8) * SR + ka + 8);  \
            }                                                                   \
            _Pragma("unroll")                                                   \
            for (int tj = 0; tj < 2; tj++) {                                    \
                int col = wn * 16 + tj * 8 + r;                                 \
                bh[tj][0] = *(const uint32_t*)(Bh + col * SR + ka);             \
                bh[tj][1] = *(const uint32_t*)(Bh + col * SR + ka + 8);         \
                bl[tj][0] = *(const uint32_t*)(Bl + col * SR + ka);             \
                bl[tj][1] = *(const uint32_t*)(Bl + col * SR + ka + 8);         \
            }                                                                   \
            _Pragma("unroll")                                                   \
            for (int ti = 0; ti < 2; ti++)                                      \
                _Pragma("unroll")                                               \
                for (int tj = 0; tj < 2; tj++) {                                \
                    mma16816(acc[ti][tj], ah[ti], bh[tj]);                      \
                    mma16816(acc[ti][tj], ah[ti], bl[tj]);                      \
                    mma16816(acc[ti][tj], al2[ti], bh[tj]);                     \
                }                                                               \
        }                                                                       \
    } while (0)

    LDG64(0, xA, xB);
    #pragma unroll 1
    for (int c = 0; c < 8; c += 2) {
        LDG64((c + 1) << 5, yA, yB);
        STS64(0, xA, xB);
        __syncthreads();
        COMP64(0);
        if (c + 2 < 8) LDG64((c + 2) << 5, xA, xB);
        STS64(1, yA, yB);
        __syncthreads();
        COMP64(1);
    }
    #undef LDG64
    #undef STS64
    #undef COMP64

    __syncthreads();  // done reading stages; tail reuses smem

    // epilogue: k = relu(acc+bias) -> gmem + smem split
    #pragma unroll
    for (int ti = 0; ti < 2; ti++) {
        int lr = wm * 32 + ti * 16 + r;
        #pragma unroll
        for (int tj = 0; tj < 2; tj++) {
            int col = wn * 16 + tj * 8 + cq;
            float b0 = __ldg(bias + col), b1 = __ldg(bias + col + 1);
            float v00 = fmaxf(acc[ti][tj][0] + b0, 0.f);
            float v01 = fmaxf(acc[ti][tj][1] + b1, 0.f);
            float v10 = fmaxf(acc[ti][tj][2] + b0, 0.f);
            float v11 = fmaxf(acc[ti][tj][3] + b1, 0.f);
            *(float2*)&C[(size_t)(m0 + lr) * 64 + col]     = make_float2(v00, v01);
            *(float2*)&C[(size_t)(m0 + lr + 8) * 64 + col] = make_float2(v10, v11);
            uint32_t hi, lo;
            split2(v00, v01, hi, lo);
            *(uint32_t*)(sm + U_KH + lr * SR2 + col) = hi;
            *(uint32_t*)(sm + U_KL + lr * SR2 + col) = lo;
            split2(v10, v11, hi, lo);
            *(uint32_t*)(sm + U_KH + (lr + 8) * SR2 + col) = hi;
            *(uint32_t*)(sm + U_KL + (lr + 8) * SR2 + col) = lo;
        }
    }
    // Wpa split
    #pragma unroll
    for (int i = t; i < 4096; i += 256) {
        int rw = i >> 6, cw = i & 63;
        float w = __ldg(W2p + i);
        __nv_bfloat16 h = __float2bfloat16_rn(w);
        sm[U_WH + rw * SR2 + cw] = h;
        sm[U_WL + rw * SR2 + cw] = __float2bfloat16_rn(w - __bfloat162float(h));
    }
    __syncthreads();

    float acc2[2][2][4] = {};
    #pragma unroll
    for (int ks = 0; ks < 4; ks++) {
        const int ka = ks * 16 + cq;
        uint32_t ah[2][4], al2[2][4], bh[2][2], bl[2][2];
        #pragma unroll
        for (int ti = 0; ti < 2; ti++) {
            int row = wm * 32 + ti * 16 + r;
            ah[ti][0] = *(const uint32_t*)(sm + U_KH + row * SR2 + ka);
            ah[ti][1] = *(const uint32_t*)(sm + U_KH + (row + 8) * SR2 + ka);
            ah[ti][2] = *(const uint32_t*)(sm + U_KH + row * SR2 + ka + 8);
            ah[ti][3] = *(const uint32_t*)(sm + U_KH + (row + 8) * SR2 + ka + 8);
            al2[ti][0] = *(const uint32_t*)(sm + U_KL + row * SR2 + ka);
            al2[ti][1] = *(const uint32_t*)(sm + U_KL + (row + 8) * SR2 + ka);
            al2[ti][2] = *(const uint32_t*)(sm + U_KL + row * SR2 + ka + 8);
            al2[ti][3] = *(const uint32_t*)(sm + U_KL + (row + 8) * SR2 + ka + 8);
        }
        #pragma unroll
        for (int tj = 0; tj < 2; tj++) {
            int col = wn * 16 + tj * 8 + r;
            bh[tj][0] = *(const uint32_t*)(sm + U_WH + col * SR2 + ka);
            bh[tj][1] = *(const uint32_t*)(sm + U_WH + col * SR2 + ka + 8);
            bl[tj][0] = *(const uint32_t*)(sm + U_WL + col * SR2 + ka);
            bl[tj][1] = *(const uint32_t*)(sm + U_WL + col * SR2 + ka + 8);
        }
        #pragma unroll
        for (int ti = 0; ti < 2; ti++)
            #pragma unroll
            for (int tj = 0; tj < 2; tj++) {
                mma16816(acc2[ti][tj], ah[ti], bh[tj]);
                mma16816(acc2[ti][tj], ah[ti], bl[tj]);
                mma16816(acc2[ti][tj], al2[ti], bh[tj]);
            }
    }
    #pragma unroll
    for (int ti = 0; ti < 2; ti++) {
        int row = m0 + wm * 32 + ti * 16 + r;
        #pragma unroll
        for (int tj = 0; tj < 2; tj++) {
            int col = wn * 16 + tj * 8 + cq;
            float b0 = __ldg(b2p + col), b1 = __ldg(b2p + col + 1);
            *(float2*)&C2[(size_t)row * 64 + col] =
                make_float2(acc2[ti][tj][0] + b0, acc2[ti][tj][1] + b1);
            *(float2*)&C2[(size_t)(row + 8) * 64 + col] =
                make_float2(acc2[ti][tj][2] + b0, acc2[ti][tj][3] + b1);
        }
    }
}

// ---------------- r + ra fused (SIMT fp32, exact): grid (1,64) ----------------
__global__ void __launch_bounds__(256)
r_ra_kernel(const float* __restrict__ A, const float* __restrict__ B,
            const float* __restrict__ bias, const float* __restrict__ Wra,
            const float* __restrict__ bra,
            float* __restrict__ R, float* __restrict__ RA) {
    __shared__ float As[16][12];
    __shared__ float Bs[16][68];
    __shared__ float rs[8][66];
    __shared__ float Ws[64][65];
    const int t  = threadIdx.x;
    const int tx = t % 32;
    const int ty = t / 32;
    const int m0 = blockIdx.y * 8;
    const int K = 256, N = 64;
    float a0 = 0.f, a1 = 0.f;

    if (blockIdx.y == 0 && t < 64) {    // zero small accumulators (ordered via evR)
        g_Spa[t] = 0.f; g_Sra[t] = 0.f; g_prot[t] = 0.f;
    }

    for (int k0 = 0; k0 < K; k0 += 16) {
        for (int i = t; i < 32; i += 256) {
            int rr = i / 4, cc = (i % 4) * 4;
            float4 v = *(const float4*)&A[(m0 + rr) * K + k0 + cc];
            As[cc + 0][rr] = v.x; As[cc + 1][rr] = v.y;
            As[cc + 2][rr] = v.z; As[cc + 3][rr] = v.w;
        }
        for (int i = t; i < 256; i += 256) {
            int rr = i / 4, cc = (i % 4) * 4;
            float4 v = *(const float4*)&B[(rr) * K + k0 + cc];
            Bs[cc + 0][rr] = v.x; Bs[cc + 1][rr] = v.y;
            Bs[cc + 2][rr] = v.z; Bs[cc + 3][rr] = v.w;
        }
        __syncthreads();
        #pragma unroll
        for (int kk = 0; kk < 16; kk++) {
            float a = As[kk][ty];
            a0 = fmaf(a, Bs[kk][tx * 2 + 0], a0);
            a1 = fmaf(a, Bs[kk][tx * 2 + 1], a1);
        }
        __syncthreads();
    }
    {
        int c0 = tx * 2;
        float v0 = fmaxf(a0 + bias[c0], 0.f);
        float v1 = fmaxf(a1 + bias[c0 + 1], 0.f);
        rs[ty][c0] = v0; rs[ty][c0 + 1] = v1;
        *(float2*)&R[(size_t)(m0 + ty) * N + c0] = make_float2(v0, v1);
    }
    for (int i = t; i < 4096; i += 256) Ws[i >> 6][i & 63] = Wra[i];
    __syncthreads();
    {
        int j = t & 63, g = t >> 6;
        float s0 = 0.f, s1 = 0.f;
        #pragma unroll
        for (int c = 0; c < 64; c++) {
            float w = Ws[j][c];
            s0 = fmaf(rs[g][c], w, s0);
            s1 = fmaf(rs[g + 4][c], w, s1);
        }
        float bj = bra[j];
        RA[(size_t)(m0 + g) * 64 + j]     = s0 + bj;
        RA[(size_t)(m0 + g + 4) * 64 + j] = s1 + bj;
    }
}

// ---------------- abs-sum double reduction (scalar FFMA-imm, abs folded) -------
// g = t>>6 owns 32 l, j = t&63; smem combine for Sr. Best-measured variant (21.15us).
__global__ void __launch_bounds__(256, 2)
relusum_kernel(const float* __restrict__ ra, const float* __restrict__ pa) {
    extern __shared__ float smf[];
    float* ra_s = smf;             // 64*64
    float* sr_s = smf + 64 * 64;   // 4*64*64
    int t = threadIdx.x;
    int j = t & 63, g = t >> 6;
    int l0 = blockIdx.x * 128;
    int q0 = blockIdx.y * 64;
    int lb = l0 + g * 32;

    float pa_loc[32], sp_loc[32];
    #pragma unroll
    for (int li = 0; li < 32; li++) {
        pa_loc[li] = pa[(lb + li) * 64 + j];
        sp_loc[li] = 0.f;
    }
    for (int i = t; i < 1024; i += 256)
        ((float4*)ra_s)[i] = ((const float4*)(ra + q0 * 64))[i];
    __syncthreads();

    if (blockIdx.y == 0) {            // pa column partial sums
        float s = 0.f;
        #pragma unroll
        for (int li = 0; li < 32; li++) s += pa_loc[li];
        atomicAdd(&g_Spa[j], s);
    }
    if (blockIdx.x == 0) {            // ra column partial sums
        float s = 0.f;
        #pragma unroll
        for (int qq = 0; qq < 16; qq++) s += ra_s[(g * 16 + qq) * 64 + j];
        atomicAdd(&g_Sra[j], s);
    }

    #define FMA1(d, a, c) asm("fma.rn.f32 %0, %1, 0f3F800000, %2;" : "=f"(d) : "f"(a), "f"(c))
    #define ABSF(d, a)    asm("abs.f32 %0, %1;" : "=f"(d) : "f"(a))
    #define ACC1(d, a)    asm("fma.rn.f32 %0, %1, 0f3F800000, %0;" : "+f"(d) : "f"(a))
    #pragma unroll 2
    for (int q = 0; q < 64; q++) {
        float raq = ra_s[q * 64 + j];
        float s0 = 0.f, s1 = 0.f, s2 = 0.f, s3 = 0.f;
        #pragma unroll
        for (int li = 0; li < 32; li += 4) {
            float v0, v1, v2, v3, a0, a1, a2, a3;
            FMA1(v0, pa_loc[li + 0], raq);
            FMA1(v1, pa_loc[li + 1], raq);
            FMA1(v2, pa_loc[li + 2], raq);
            FMA1(v3, pa_loc[li + 3], raq);
            ABSF(a0, v0); ABSF(a1, v1); ABSF(a2, v2); ABSF(a3, v3);
            ACC1(sp_loc[li + 0], a0); ACC1(sp_loc[li + 1], a1);
            ACC1(sp_loc[li + 2], a2); ACC1(sp_loc[li + 3], a3);
            ACC1(s0, a0); ACC1(s1, a1); ACC1(s2, a2); ACC1(s3, a3);
        }
        sr_s[(g * 64 + q) * 64 + j] = (s0 + s1) + (s2 + s3);
    }
    #undef FMA1
    #undef ABSF
    #undef ACC1
    __syncthreads();

    #pragma unroll
    for (int li = 0; li < 32; li++)
        atomicAdd(&g_Sp[(lb + li) * 64 + j], sp_loc[li]);
    for (int idx = t; idx < 4096; idx += 256) {
        int q = idx >> 6, jj = idx & 63;
        float s = (sr_s[q * 64 + jj] + sr_s[(64 + q) * 64 + jj]) +
                  (sr_s[(128 + q) * 64 + jj] + sr_s[(192 + q) * 64 + jj]);
        atomicAdd(&g_Sr[(q0 + q) * 64 + jj], s);
    }
}

// ---------------- p_gate / prot: S_p = 0.5*(Q*pa + Sra + abs) ----------------
__global__ void __launch_bounds__(256)
pgate_prot_kernel(const float* __restrict__ Wa, const float* __restrict__ ba) {
    __shared__ float Ws[64][65];
    __shared__ float sps[64][64];
    __shared__ float red[4][64];
    int t = threadIdx.x;
    int j = t & 63, g = t >> 6;
    int l0 = blockIdx.x * 64;
    for (int i = t; i < 4096; i += 256) Ws[i >> 6][i & 63] = Wa[i];
    for (int i = t; i < 1024; i += 256) {
        float4 ab = ((const float4*)(g_Sp + l0 * 64))[i];
        float4 p4 = ((const float4*)(g_pa + l0 * 64))[i];
        int c0 = (i * 4) & 63;
        float4 sr4 = *(const float4*)(g_Sra + c0);
        float4 o;
        o.x = 0.5f * (512.f * p4.x + sr4.x + ab.x);
        o.y = 0.5f * (512.f * p4.y + sr4.y + ab.y);
        o.z = 0.5f * (512.f * p4.z + sr4.z + ab.z);
        o.w = 0.5f * (512.f * p4.w + sr4.w + ab.w);
        ((float4*)sps)[i] = o;
    }
    __syncthreads();
    float acc[16] = {};
    for (int c = 0; c < 64; c++) {
        float w = Ws[j][c];
        #pragma unroll
        for (int rr = 0; rr < 16; rr++)
            acc[rr] = fmaf(sps[rr * 4 + g][c], w, acc[rr]);
    }
    float bj = ba[j];
    float mx = 0.f;
    #pragma unroll
    for (int rr = 0; rr < 16; rr++) {
        int l = l0 + rr * 4 + g;
        float gate = 1.f / (1.f + expf(-(acc[rr] * (1.f / 512.f) + bj)));
        float cand = g_k[l * 64 + j] * (1.f + gate);  // k>=0 -> cand>=0
        mx = fmaxf(mx, cand);
    }
    red[g][j] = mx;
    __syncthreads();
    if (t < 64) {
        float m = fmaxf(fmaxf(red[0][t], red[1][t]), fmaxf(red[2][t], red[3][t]));
        atomicMax(reinterpret_cast<unsigned*>(&g_prot[t]), __float_as_uint(m));
    }
}

// ---------------- r_gate, ctx, MLP: S_r = 0.5*(L*ra + Spa + abs) ----------------
__global__ void __launch_bounds__(256)
final_kernel(const float* __restrict__ Wa,  const float* __restrict__ ba,
             const float* __restrict__ Wf1, const float* __restrict__ bf1,
             const float* __restrict__ Wf2, const float* __restrict__ bf2,
             const float* __restrict__ Wf3, const float* __restrict__ bf3,
             float* __restrict__ out) {
    __shared__ float Ws[64][65];
    __shared__ float srs[8][64];
    __shared__ float rs[8][64];
    __shared__ float ctx[8][128];
    __shared__ float h1s[8][256];
    __shared__ float h2s[8][128];
    __shared__ float prot_s[64];
    int t = threadIdx.x;
    int q0 = blockIdx.x * 8;
    for (int i = t; i < 4096; i += 256) Ws[i >> 6][i & 63] = Wa[i];
    if (t < 128) {
        float4 ab  = ((const float4*)(g_Sr + q0 * 64))[t];
        float4 ra4 = ((const float4*)(g_ra + q0 * 64))[t];
        int c0 = (t * 4) & 63;
        float4 sp4 = *(const float4*)(g_Spa + c0);
        float4 o;
        o.x = 0.5f * (4096.f * ra4.x + sp4.x + ab.x);
        o.y = 0.5f * (4096.f * ra4.y + sp4.y + ab.y);
        o.z = 0.5f * (4096.f * ra4.z + sp4.z + ab.z);
        o.w = 0.5f * (4096.f * ra4.w + sp4.w + ab.w);
        ((float4*)srs)[t] = o;
        ((float4*)rs)[t]  = ((const float4*)(g_r + q0 * 64))[t];
    }
    if (t < 64) prot_s[t] = g_prot[t];
    __syncthreads();
    {
        int j = t & 63, g = t >> 6;
        float a0 = 0.f, a1 = 0.f;
        for (int c = 0; c < 64; c++) {
            float w = Ws[j][c];
            a0 = fmaf(srs[g][c], w, a0);
            a1 = fmaf(srs[g + 4][c], w, a1);
        }
        float bj = ba[j];
        float g0 = 1.f / (1.f + expf(-(a0 * (1.f / 4096.f) + bj)));
        float g1 = 1.f / (1.f + expf(-(a1 * (1.f / 4096.f) + bj)));
        ctx[g][j]          = rs[g][j]     * (1.f + g0);
        ctx[g + 4][j]      = rs[g + 4][j] * (1.f + g1);
        ctx[g][64 + j]     = prot_s[j];
        ctx[g + 4][64 + j] = prot_s[j];
    }
    __syncthreads();
    {
        float acc[8] = {};
        const float* wrow = Wf1 + t * 128;
        for (int c = 0; c < 128; c++) {
            float w = wrow[c];
            #pragma unroll
            for (int qq = 0; qq < 8; qq++)
                acc[qq] = fmaf(ctx[qq][c], w, acc[qq]);
        }
        float bj = bf1[t];
        #pragma unroll
        for (int qq = 0; qq < 8; qq++) {
            float v = acc[qq] + bj;
            h1s[qq][t] = v >= 0.f ? v : 0.01f * v;
        }
    }
    __syncthreads();
    {
        int jj = t & 127, h = t >> 7;
        float acc[4] = {};
        const float* wrow = Wf2 + jj * 256;
        for (int c = 0; c < 256; c++) {
            float w = wrow[c];
            #pragma unroll
            for (int qq = 0; qq < 4; qq++)
                acc[qq] = fmaf(h1s[h * 4 + qq][c], w, acc[qq]);
        }
        float bj = bf2[jj];
        #pragma unroll
        for (int qq = 0; qq < 4; qq++) {
            float v = acc[qq] + bj;
            h2s[h * 4 + qq][jj] = v >= 0.f ? v : 0.01f * v;
        }
    }
    __syncthreads();
    {
        int w = t >> 5, lane = t & 31;
        float s = 0.f;
        #pragma unroll
        for (int k4 = 0; k4 < 4; k4++)
            s = fmaf(h2s[w][lane + k4 * 32], Wf3[lane + k4 * 32], s);
        #pragma unroll
        for (int off = 16; off > 0; off >>= 1)
            s += __shfl_down_sync(0xffffffff, s, off);
        if (lane == 0) out[q0 + w] = s + bf3[0];
    }
}

// ---------------- launch ----------------
extern "C" void kernel_launch(void* const* d_in, const int* in_sizes, int n_in,
                              void* d_out, int out_size) {
    const float* reactions = (const float*)d_in[0];
    const float* protein   = (const float*)d_in[1];
    const float* Wc  = (const float*)d_in[2];
    const float* bc  = (const float*)d_in[3];
    const float* W1  = (const float*)d_in[4];
    const float* b1  = (const float*)d_in[5];
    const float* W2  = (const float*)d_in[6];
    const float* b2  = (const float*)d_in[7];
    const float* Wa  = (const float*)d_in[8];
    const float* ba  = (const float*)d_in[9];
    const float* Wpa = (const float*)d_in[10];
    const float* bpa = (const float*)d_in[11];
    const float* Wra = (const float*)d_in[12];
    const float* bra = (const float*)d_in[13];
    const float* Wf1 = (const float*)d_in[14];
    const float* bf1 = (const float*)d_in[15];
    const float* Wf2 = (const float*)d_in[16];
    const float* bf2 = (const float*)d_in[17];
    const float* Wf3 = (const float*)d_in[18];
    const float* bf3 = (const float*)d_in[19];
    float* out = (float*)d_out;

    float *pP, *pK, *pPa, *pR, *pRa, *pSp, *pSr;
    cudaGetSymbolAddress((void**)&pP,  g_p);
    cudaGetSymbolAddress((void**)&pK,  g_k);
    cudaGetSymbolAddress((void**)&pPa, g_pa);
    cudaGetSymbolAddress((void**)&pR,  g_r);
    cudaGetSymbolAddress((void**)&pRa, g_ra);
    cudaGetSymbolAddress((void**)&pSp, g_Sp);
    cudaGetSymbolAddress((void**)&pSr, g_Sr);

    static cudaStream_t s1 = nullptr, s2 = nullptr;
    static cudaEvent_t evF = nullptr, evR = nullptr, evZ = nullptr;
    if (!s1) {
        cudaStreamCreateWithFlags(&s1, cudaStreamNonBlocking);
        cudaStreamCreateWithFlags(&s2, cudaStreamNonBlocking);
        cudaEventCreateWithFlags(&evF, cudaEventDisableTiming);
        cudaEventCreateWithFlags(&evR, cudaEventDisableTiming);
        cudaEventCreateWithFlags(&evZ, cudaEventDisableTiming);
        cudaFuncSetAttribute(gemm_p,
                             cudaFuncAttributeMaxDynamicSharedMemorySize, GEMM_SMEM_BYTES);
        cudaFuncSetAttribute(gemm64_kpa,
                             cudaFuncAttributeMaxDynamicSharedMemorySize, GEMM64_SMEM_BYTES);
        cudaFuncSetAttribute(relusum_kernel,
                             cudaFuncAttributeMaxDynamicSharedMemorySize,
                             (64 * 64 + 4 * 64 * 64) * 4);
    }

    // ---- fork ----
    cudaEventRecord(evF, 0);
    cudaStreamWaitEvent(s1, evF, 0);
    cudaStreamWaitEvent(s2, evF, 0);

    // s2: zero the abs-sum accumulators
    cudaMemsetAsync(pSp, 0, (size_t)LN * 64 * sizeof(float), s2);
    cudaMemsetAsync(pSr, 0, (size_t)QN * 64 * sizeof(float), s2);
    cudaEventRecord(evZ, s2);

    // s1: reaction branch r -> ra (also zeroes g_Spa/g_Sra/g_prot)
    r_ra_kernel<<<dim3(1, 64), 256, 0, s1>>>(reactions, W2, b2, Wra, bra, pR, pRa);
    cudaEventRecord(evR, s1);

    // main: protein chain  p -> (k + pa fused)
    gemm_p<<<dim3(4, 32), 256, GEMM_SMEM_BYTES>>>(protein, Wc, bc, 1024, 256, pP);
    gemm64_kpa<<<dim3(1, 64), 256, GEMM64_SMEM_BYTES>>>(pP, W1, b1, pK, Wpa, bpa, pPa);

    // ---- join ----
    cudaStreamWaitEvent(0, evR, 0);
    cudaStreamWaitEvent(0, evZ, 0);

    // abs-sum double reduction, scalar FFMA-imm (relu = (x+|x|)/2 downstream)
    const int rsmem = (64 * 64 + 4 * 64 * 64) * 4;
    relusum_kernel<<<dim3(32, 8), 256, rsmem>>>(pRa, pPa);

    pgate_prot_kernel<<<64, 256>>>(Wa, ba);
    final_kernel<<<64, 256>>>(Wa, ba, Wf1, bf1, Wf2, bf2, Wf3, bf3, out);
}